// round 14
// baseline (speedup 1.0000x reference)
#include <cuda_runtime.h>
#include <cuda_fp16.h>
#include <math.h>

#define B_    16
#define NPTS  2048
#define PCTR  256
#define KNB   32
#define HW    1920
#define INFEA 64
#define MTOT  131072
#define EPSBN 1e-5f
#define DIST_ 0.5f
#define OUTSTRIDE 5242880   // 640*8192

// ---------------- scratch ----------------
__device__ __half g_X0h[96 * MTOT];   // channels 67..95 stay zero
__device__ __half g_Y1h[64 * MTOT];
__device__ __half g_Y2h[128 * MTOT];
__device__ __half g_Y3h[128 * MTOT];
__device__ __half g_Y4h[256 * MTOT];
__device__ float  g_imgT[B_ * HW * 192];    // pixel-major fused img1+img2
__device__ __half g_featT[B_ * NPTS * 64];  // pixel-major feat (half)
__device__ int    g_idx[MTOT];
__device__ int    g_ridx[MTOT];
__device__ float  g_vmask[B_ * PCTR];
__device__ __half g_Wp1h[64 * 96];
__device__ __half g_Wp2h[128 * 64];
__device__ __half g_Wp3h[128 * 128];
__device__ __half g_Wp4h[256 * 128];
__device__ float  g_sum[4][256];
__device__ float  g_sq[4][256];
__device__ float  g_sc[4][256];
__device__ float  g_sh[4][256];
__device__ __half g_scH[4][256];
__device__ __half g_shH[4][256];
__device__ unsigned g_cnt[6];

__device__ __forceinline__ void cp16(void* dst_smem, const void* src) {
    unsigned d = (unsigned)__cvta_generic_to_shared(dst_smem);
    asm volatile("cp.async.cg.shared.global [%0], [%1], 16;" :: "r"(d), "l"(src));
}
__device__ __forceinline__ void ldsm_x4(unsigned* r, unsigned a) {
    asm volatile("ldmatrix.sync.aligned.m8n8.x4.shared.b16 {%0,%1,%2,%3}, [%4];"
        : "=r"(r[0]), "=r"(r[1]), "=r"(r[2]), "=r"(r[3]) : "r"(a));
}
__device__ __forceinline__ void ldsm_x4_t(unsigned* r, unsigned a) {
    asm volatile("ldmatrix.sync.aligned.m8n8.x4.trans.shared.b16 {%0,%1,%2,%3}, [%4];"
        : "=r"(r[0]), "=r"(r[1]), "=r"(r[2]), "=r"(r[3]) : "r"(a));
}
__device__ __forceinline__ unsigned nrm2(unsigned v, unsigned s, unsigned t) {
    __half2 r = __hfma2(*(__half2*)&v, *(__half2*)&s, *(__half2*)&t);
    r = __hmax2(r, __half2(__half(0.f), __half(0.f)));
    return *(unsigned*)&r;
}

// ---------------- depth-ball query (+ zero stats & counters) ----------------
__global__ void k_idx(const float* __restrict__ pc,
                      const float* __restrict__ npc,
                      const int*   __restrict__ qv1)
{
    __shared__ float zs[NPTS];
    __shared__ int   stage[8][32];
    const int b   = blockIdx.x;
    const int tid = threadIdx.x;

    if (b == 0) {
        float* ps = &g_sum[0][0];
        float* pq = &g_sq[0][0];
        for (int i = tid; i < 4 * 256; i += 256) { ps[i] = 0.f; pq[i] = 0.f; }
        if (tid < 6) g_cnt[tid] = 0u;
    }
    for (int i = tid; i < NPTS; i += 256) zs[i] = pc[(b * 3 + 2) * NPTS + i];
    __syncthreads();

    const int w = tid >> 5, lane = tid & 31;
    for (int jj = 0; jj < 32; jj++) {
        const int j = w * 32 + jj;
        const float cz = npc[(b * 3 + 2) * PCTR + j];
        int cnt = 0;
        for (int c = 0; c < NPTS / 32; c++) {
            const int n = c * 32 + lane;
            const bool hit = fabsf(zs[n] - cz) < DIST_;
            const unsigned bal = __ballot_sync(0xffffffffu, hit);
            if (hit) {
                const int pos = cnt + __popc(bal & ((1u << lane) - 1u));
                if (pos < 32) stage[w][pos] = n;
            }
            cnt += __popc(bal);
            if (cnt >= 32) break;
        }
        __syncwarp();
        const int cc = min(cnt, 32);
        const int first = (cnt > 0) ? stage[w][0] : 0;
        const int v = (lane < cc) ? stage[w][lane] : first;
        const int gbase = (b * PCTR + j) * KNB;
        g_idx[gbase + lane]  = v;
        g_ridx[gbase + lane] = qv1[b * NPTS + v];
        if (lane == 0) g_vmask[b * PCTR + j] = (cnt > 0) ? 1.f : 0.f;
        __syncwarp();
    }
}

// ---------------- weight packing ----------------
__device__ __forceinline__ void packW(const float* w, __half* dst,
                                      int M, int CIN, int CINP, int tid, int nthr)
{
    const int tot = M * CINP;
    for (int i = tid; i < tot; i += nthr) {
        const int m = i / CINP, k = i - m * CINP;
        dst[i] = __float2half((k < CIN) ? w[m * CIN + k] : 0.f);
    }
}

__global__ void k_prep(const float* __restrict__ w1, const float* __restrict__ w2,
                       const float* __restrict__ w3, const float* __restrict__ w4)
{
    const int tid = blockIdx.x * blockDim.x + threadIdx.x;
    const int nthr = gridDim.x * blockDim.x;
    packW(w1, g_Wp1h, 64, 67, 96, tid, nthr);
    packW(w2, g_Wp2h, 128, 64, 64, tid, nthr);
    packW(w3, g_Wp3h, 128, 128, 128, tid, nthr);
    packW(w4, g_Wp4h, 256, 128, 128, tid, nthr);
}

// ---------------- feat transpose: [B][64][N] -> [B][N][64] half ----------------
__global__ void k_tfeat(const float* __restrict__ feat)
{
    __shared__ float tile[32][33];
    const int b  = blockIdx.z;
    const int p0 = blockIdx.x * 32;
    const int c0 = blockIdx.y * 32;
    const int tx = threadIdx.x, ty = threadIdx.y;
    tile[ty][tx] = feat[(size_t)(b * 64 + c0 + ty) * NPTS + p0 + tx];
    __syncthreads();
    g_featT[((size_t)b * NPTS + p0 + ty) * 64 + c0 + tx] = __float2half(tile[tx][ty]);
}

// ---------------- gather X0 (half) + embedded img-transpose blocks ----------------
__global__ void k_gather(const float* __restrict__ pc,
                         const float* __restrict__ npc,
                         const float* __restrict__ img1,
                         const float* __restrict__ img2,
                         int NG)
{
    __shared__ __align__(16) __half sm[64 * 32];
    __shared__ float tile[32][33];
    __shared__ int    s_idx[32];
    __shared__ float  s_np[3];
    const int t = threadIdx.x;

    if ((int)blockIdx.x >= NG) {
        // img transpose blocks: [B][C][HW] -> [B][HW][192]
        const int wb = blockIdx.x - NG;
        const int WT = gridDim.x - NG;
        const int tx = t & 31, tyb = t >> 5;   // 8 rows per pass
        for (int tt = wb; tt < B_ * 60 * 6; tt += WT) {
            const int b = tt / 360;
            const int r = tt - b * 360;
            const int pt = r / 6, ct = r - pt * 6;
            const int p0 = pt * 32, c0 = ct * 32;
            __syncthreads();
            for (int yy = tyb; yy < 32; yy += 8) {
                const int c = c0 + yy;
                const float* src = (c < 64) ? &img1[(size_t)(b * 64 + c) * HW]
                                            : &img2[(size_t)(b * 128 + (c - 64)) * HW];
                tile[yy][tx] = src[p0 + tx];
            }
            __syncthreads();
            for (int yy = tyb; yy < 32; yy += 8)
                g_imgT[((size_t)b * HW + p0 + yy) * 192 + c0 + tx] = tile[tx][yy];
        }
        return;
    }

    const int g = blockIdx.x;
    const int b = g >> 8;
    const int j = g & 255;
    const int mbase = g * KNB;

    if (t < 32) s_idx[t] = g_idx[mbase + t];
    if (t >= 32 && t < 35) s_np[t - 32] = npc[(b * 3 + (t - 32)) * PCTR + j];
    __syncthreads();

    // pc channels (3 x 32)
    if (t < 96) {
        const int c = t >> 5, k = t & 31;
        g_X0h[c * MTOT + mbase + k] =
            __float2half(pc[(b * 3 + c) * NPTS + s_idx[k]] - s_np[c]);
    }

    // feat: k = lane (32 pixels/warp), q = warp (channel chunk) -> conflict-light STS
    {
        const int k = t & 31, q = t >> 5;
        const uint4 v = *(const uint4*)&g_featT[((size_t)b * NPTS + s_idx[k]) * 64 + q * 8];
        const __half* hv = (const __half*)&v;
#pragma unroll
        for (int jj = 0; jj < 8; jj++) sm[(q * 8 + jj) * 32 + k] = hv[jj];
    }
    __syncthreads();

    // write X0 channel-major: 64 ch x 4 uint4
    {
        const int c = t >> 2, q = t & 3;
        *(uint4*)&g_X0h[(3 + c) * MTOT + mbase + q * 8] = *(uint4*)&sm[c * 32 + q * 8];
    }
}

// ---------------- multi-tile fp16 TC GEMM + embedded writer blocks ----------------
// WMODE 0: pure GEMM. WMODE 1: writers emit out = relu(wsc*wY+wsh)*vm.
// WMODE 2: writers emit rgb1/rgb2 from pixel-major imgT (coalesced).
template <int BM, int CTOT, int CIN, int TILES, int THREADS, bool NORM_IN, int WMODE>
__global__ void __launch_bounds__(THREADS)
k_gemm_h(const __half* __restrict__ Wp, const __half* __restrict__ X,
         __half* __restrict__ Y,
         const __half* __restrict__ iscH, const __half* __restrict__ ishH,
         float* __restrict__ osum, float* __restrict__ osq,
         const float* __restrict__ gam, const float* __restrict__ bet,
         float* __restrict__ sc, float* __restrict__ sh,
         __half* __restrict__ scH, __half* __restrict__ shH,
         unsigned* __restrict__ cnt,
         float* __restrict__ out,
         const __half* __restrict__ wY,
         const float* __restrict__ wsc, const float* __restrict__ wsh,
         const float* __restrict__ imgT,
         int GXG, int ngemm, int wC, int wcbase)
{
    constexpr int BN = 128, BK = 32, PIPE = 3;
    constexpr int NITER = CIN / BK;
    constexpr int TOT = TILES * NITER;
    constexpr int WROW = CIN + 8;
    constexpr int BROW = BN + 8;
    constexpr int WARPS_M = THREADS / 128;
    constexpr int WTM = BM / WARPS_M;
    constexpr int MI = WTM / 16;
    constexpr int WCH = CIN / 8;

    const int tid = threadIdx.x;
    extern __shared__ __align__(16) __half dsm[];

    // ---------- embedded writer blocks ----------
    if (WMODE != 0 && (int)blockIdx.x >= GXG) {
        const int wb  = blockIdx.x - GXG;
        const int WBn = gridDim.x - GXG;
        if (WMODE == 1) {
            const int T = wC * (MTOT / 8);
            for (int e = wb * THREADS + tid; e < T; e += WBn * THREADS) {
                const int c = e / (MTOT / 8);
                const int m = (e - c * (MTOT / 8)) * 8;
                const uint4 r = *(const uint4*)&wY[(size_t)c * MTOT + m];
                const __half* h = (const __half*)&r;
                const float s = wsc[c], t = wsh[c];
                const float vm = g_vmask[m >> 5];
                const int bb = m >> 13, rem = m & 8191;
                float* op = &out[(long)bb * OUTSTRIDE + (long)(wcbase + c) * 8192 + rem];
                *(float4*)op = make_float4(
                    fmaxf(__half2float(h[0]) * s + t, 0.f) * vm,
                    fmaxf(__half2float(h[1]) * s + t, 0.f) * vm,
                    fmaxf(__half2float(h[2]) * s + t, 0.f) * vm,
                    fmaxf(__half2float(h[3]) * s + t, 0.f) * vm);
                *(float4*)(op + 4) = make_float4(
                    fmaxf(__half2float(h[4]) * s + t, 0.f) * vm,
                    fmaxf(__half2float(h[5]) * s + t, 0.f) * vm,
                    fmaxf(__half2float(h[6]) * s + t, 0.f) * vm,
                    fmaxf(__half2float(h[7]) * s + t, 0.f) * vm);
            }
        } else {
            // rgb writer: coalesced rows from imgT, smem-staged transpose to out
            float* sm = (float*)dsm;                 // [192][33] stage
            int*   rp = (int*)(sm + 192 * 33);       // 32 pixel ids
            float* vmp = sm + 192 * 33 + 32;
            for (int g0 = wb; g0 < B_ * PCTR; g0 += WBn) {
                const int b = g0 >> 8, j = g0 & 255;
                if (tid < 32) rp[tid] = g_ridx[g0 * KNB + tid];
                if (tid == 32) vmp[0] = g_vmask[g0];
                __syncthreads();
                const float vm = vmp[0];
                for (int e = tid; e < 32 * 48; e += THREADS) {
                    const int k = e / 48, c4 = e - k * 48;
                    const float4 v =
                        ((const float4*)&imgT[((size_t)b * HW + rp[k]) * 192])[c4];
                    sm[(c4 * 4 + 0) * 33 + k] = v.x;
                    sm[(c4 * 4 + 1) * 33 + k] = v.y;
                    sm[(c4 * 4 + 2) * 33 + k] = v.z;
                    sm[(c4 * 4 + 3) * 33 + k] = v.w;
                }
                __syncthreads();
                const long ob = (long)b * OUTSTRIDE + (long)j * 32;
                for (int e = tid; e < 192 * 8; e += THREADS) {
                    const int c = e >> 3, q = e & 7;
                    const int oc = (c < 64) ? 64 + c : 192 + c;   // 256+(c-64)
                    const float* sp = &sm[c * 33 + q * 4];
                    float4 o = make_float4(sp[0] * vm, sp[1] * vm, sp[2] * vm, sp[3] * vm);
                    *(float4*)&out[ob + (long)oc * 8192 + q * 4] = o;
                }
                __syncthreads();
            }
        }
        return;
    }

    // ---------- GEMM blocks ----------
    __half* Ws = dsm;                               // BM * WROW
    __half* Bs = Ws + BM * WROW;                    // PIPE * BK * BROW
    __half* sS = Bs + PIPE * BK * BROW;             // CIN
    __half* sT = sS + CIN;                          // CIN
    __shared__ int s_last;

    const int lane = tid & 31;
    const int warp = tid >> 5;
    const int wm0  = (warp >> 2) * WTM;
    const int wn0  = (warp & 3) * 32;
    const int bn0  = blockIdx.x * (BN * TILES);
    const int bm0  = blockIdx.y * BM;
    const int grp  = lane >> 2;
    const int tig  = lane & 3;

    const unsigned ws_u = (unsigned)__cvta_generic_to_shared(Ws);
    const unsigned bs_u = (unsigned)__cvta_generic_to_shared(Bs);

    for (int f = tid; f < BM * WCH; f += THREADS) {
        const int m = f / WCH, ch = f % WCH;
        cp16(&Ws[m * WROW + ch * 8], &Wp[(size_t)(bm0 + m) * CIN + ch * 8]);
    }
    if (NORM_IN) {
        for (int e = tid; e < CIN; e += THREADS) { sS[e] = iscH[e]; sT[e] = ishH[e]; }
    }
    asm volatile("cp.async.commit_group;");

    auto cpB = [&](int g) {
        const int stg = g % PIPE;
        const int tile = g / NITER, it = g - tile * NITER;
        const int nb = bn0 + tile * BN;
        for (int e = tid; e < BK * (BN / 8); e += THREADS) {
            const int kk = e >> 4, ch = e & 15;
            cp16(&Bs[(stg * BK + kk) * BROW + ch * 8],
                 &X[(size_t)(it * BK + kk) * MTOT + nb + ch * 8]);
        }
    };
#pragma unroll
    for (int s = 0; s < PIPE - 1; s++) {
        if (s < TOT) cpB(s);
        asm volatile("cp.async.commit_group;");
    }
    asm volatile("cp.async.wait_group %0;" :: "n"(PIPE - 2));
    __syncthreads();

    float acc[MI][4][4];
#pragma unroll
    for (int mi = 0; mi < MI; mi++)
#pragma unroll
        for (int ni = 0; ni < 4; ni++)
#pragma unroll
            for (int r = 0; r < 4; r++) acc[mi][ni][r] = 0.f;

    float sSr[MI][2], sQr[MI][2];
#pragma unroll
    for (int mi = 0; mi < MI; mi++) {
        sSr[mi][0] = sSr[mi][1] = 0.f;
        sQr[mi][0] = sQr[mi][1] = 0.f;
    }

    const int a_row = (lane & 7) + ((lane >> 3) & 1) * 8;
    const int a_kq  = ((lane >> 4) & 1) * 8;
    const int b_kr  = ((lane >> 3) & 1) * 8 + (lane & 7);
    const int b_nq  = ((lane >> 4) & 1) * 8;

    for (int g = 0; g < TOT; g++) {
        const int stg = g % PIPE;
        const int tile = g / NITER, it = g - tile * NITER;
        if (g + PIPE - 1 < TOT) cpB(g + PIPE - 1);
        asm volatile("cp.async.commit_group;");

#pragma unroll
        for (int kk = 0; kk < 2; kk++) {
            const int kbase = it * BK + kk * 16;
            unsigned a[MI][4], bfr[4][2];
#pragma unroll
            for (int mi = 0; mi < MI; mi++) {
                const unsigned addr = ws_u +
                    (((wm0 + mi * 16 + a_row) * WROW) + kbase + a_kq) * 2;
                ldsm_x4(a[mi], addr);
            }
#pragma unroll
            for (int ni2 = 0; ni2 < 2; ni2++) {
                unsigned t4[4];
                const unsigned addr = bs_u + ((stg * BK + kk * 16 + b_kr) * BROW +
                                              wn0 + ni2 * 16 + b_nq) * 2;
                ldsm_x4_t(t4, addr);
                bfr[ni2 * 2][0] = t4[0]; bfr[ni2 * 2][1] = t4[1];
                bfr[ni2 * 2 + 1][0] = t4[2]; bfr[ni2 * 2 + 1][1] = t4[3];
            }
            if (NORM_IN) {
                const int k0 = kbase + 2 * tig;
                const unsigned s0 = *(const unsigned*)&sS[k0];
                const unsigned t0 = *(const unsigned*)&sT[k0];
                const unsigned s1 = *(const unsigned*)&sS[k0 + 8];
                const unsigned t1 = *(const unsigned*)&sT[k0 + 8];
#pragma unroll
                for (int ni = 0; ni < 4; ni++) {
                    bfr[ni][0] = nrm2(bfr[ni][0], s0, t0);
                    bfr[ni][1] = nrm2(bfr[ni][1], s1, t1);
                }
            }
#pragma unroll
            for (int mi = 0; mi < MI; mi++)
#pragma unroll
                for (int ni = 0; ni < 4; ni++) {
                    asm volatile(
                        "mma.sync.aligned.m16n8k16.row.col.f32.f16.f16.f32 "
                        "{%0,%1,%2,%3}, {%4,%5,%6,%7}, {%8,%9}, {%0,%1,%2,%3};"
                        : "+f"(acc[mi][ni][0]), "+f"(acc[mi][ni][1]),
                          "+f"(acc[mi][ni][2]), "+f"(acc[mi][ni][3])
                        : "r"(a[mi][0]), "r"(a[mi][1]), "r"(a[mi][2]), "r"(a[mi][3]),
                          "r"(bfr[ni][0]), "r"(bfr[ni][1]));
                }
        }

        if (it == NITER - 1) {
            const int nb = bn0 + tile * BN;
#pragma unroll
            for (int mi = 0; mi < MI; mi++) {
                const int r1 = wm0 + mi * 16 + grp;
                const int r2 = r1 + 8;
#pragma unroll
                for (int ni = 0; ni < 4; ni++) {
                    const int col = nb + wn0 + ni * 8 + tig * 2;
                    const float c0 = acc[mi][ni][0], c1 = acc[mi][ni][1];
                    const float c2 = acc[mi][ni][2], c3 = acc[mi][ni][3];
                    *(__half2*)&Y[(size_t)(bm0 + r1) * MTOT + col] = __floats2half2_rn(c0, c1);
                    *(__half2*)&Y[(size_t)(bm0 + r2) * MTOT + col] = __floats2half2_rn(c2, c3);
                    sSr[mi][0] += c0 + c1;  sQr[mi][0] += c0 * c0 + c1 * c1;
                    sSr[mi][1] += c2 + c3;  sQr[mi][1] += c2 * c2 + c3 * c3;
                    acc[mi][ni][0] = 0.f; acc[mi][ni][1] = 0.f;
                    acc[mi][ni][2] = 0.f; acc[mi][ni][3] = 0.f;
                }
            }
        }
        asm volatile("cp.async.wait_group %0;" :: "n"(PIPE - 2));
        __syncthreads();
    }

    // ---- epilogue: block stats reduction (aliases B smem) ----
    float* redS = (float*)Bs;
    float* redQ = redS + BM;
    for (int e = tid; e < BM; e += THREADS) { redS[e] = 0.f; redQ[e] = 0.f; }
    __syncthreads();
#pragma unroll
    for (int mi = 0; mi < MI; mi++) {
        const int r1 = wm0 + mi * 16 + grp;
        atomicAdd(&redS[r1], sSr[mi][0]);
        atomicAdd(&redQ[r1], sQr[mi][0]);
        atomicAdd(&redS[r1 + 8], sSr[mi][1]);
        atomicAdd(&redQ[r1 + 8], sQr[mi][1]);
    }
    __syncthreads();
    for (int e = tid; e < BM; e += THREADS) {
        atomicAdd(&osum[bm0 + e], redS[e]);
        atomicAdd(&osq[bm0 + e], redQ[e]);
    }

    // ---- last GEMM block finalizes BN scale/shift ----
    __threadfence();
    __syncthreads();
    if (tid == 0) {
        const unsigned done = atomicAdd(cnt, 1u);
        s_last = (done == (unsigned)(ngemm - 1)) ? 1 : 0;
    }
    __syncthreads();
    if (s_last) {
        __threadfence();
        for (int c = tid; c < CTOT; c += THREADS) {
            const float m = osum[c] * (1.f / (float)MTOT);
            const float v = osq[c] * (1.f / (float)MTOT) - m * m;
            const float s = gam[c] * rsqrtf(v + EPSBN);
            const float t = bet[c] - m * s;
            sc[c] = s;
            sh[c] = t;
            scH[c] = __float2half(s);
            shH[c] = __float2half(t);
        }
    }
}

// ---------------- out writer: out[cbase..cbase+C) = relu(s*Y+t)*vm (fp32) ----------------
__global__ void k_out(const __half* __restrict__ Y, int layer, int C, int cbase, int cofs,
                      float* __restrict__ out)
{
    const int T = C * (MTOT / 8);
    for (int e = blockIdx.x * blockDim.x + threadIdx.x; e < T;
         e += gridDim.x * blockDim.x) {
        const int c = e / (MTOT / 8);
        const int m = (e - c * (MTOT / 8)) * 8;
        const uint4 r = *(const uint4*)&Y[(size_t)c * MTOT + m];
        const __half* h = (const __half*)&r;
        const float s = g_sc[layer][cofs + c], t = g_sh[layer][cofs + c];
        const float vm = g_vmask[m >> 5];
        const int bb = m >> 13, rem = m & 8191;
        float* op = &out[(long)bb * OUTSTRIDE + (long)(cbase + c) * 8192 + rem];
        *(float4*)op = make_float4(
            fmaxf(__half2float(h[0]) * s + t, 0.f) * vm,
            fmaxf(__half2float(h[1]) * s + t, 0.f) * vm,
            fmaxf(__half2float(h[2]) * s + t, 0.f) * vm,
            fmaxf(__half2float(h[3]) * s + t, 0.f) * vm);
        *(float4*)(op + 4) = make_float4(
            fmaxf(__half2float(h[4]) * s + t, 0.f) * vm,
            fmaxf(__half2float(h[5]) * s + t, 0.f) * vm,
            fmaxf(__half2float(h[6]) * s + t, 0.f) * vm,
            fmaxf(__half2float(h[7]) * s + t, 0.f) * vm);
    }
}

// ---------------- launch ----------------
extern "C" void kernel_launch(void* const* d_in, const int* in_sizes, int n_in,
                              void* d_out, int out_size)
{
    const float* pc   = (const float*)d_in[0];
    const float* feat = (const float*)d_in[1];
    const float* img1 = (const float*)d_in[2];
    const float* img2 = (const float*)d_in[3];
    const int*   qv1  = (const int*)d_in[5];
    const float* npc  = (const float*)d_in[6];
    const float* w1 = (const float*)d_in[7];
    const float* g1 = (const float*)d_in[8];
    const float* b1 = (const float*)d_in[9];
    const float* w2 = (const float*)d_in[10];
    const float* g2 = (const float*)d_in[11];
    const float* b2 = (const float*)d_in[12];
    const float* w3 = (const float*)d_in[13];
    const float* g3 = (const float*)d_in[14];
    const float* b3 = (const float*)d_in[15];
    const float* w4 = (const float*)d_in[16];
    const float* g4 = (const float*)d_in[17];
    const float* b4 = (const float*)d_in[18];
    float* out = (float*)d_out;

    __half *pX0, *pY1, *pY2, *pY3, *pY4;
    __half *pW1, *pW2, *pW3, *pW4, *pScH, *pShH;
    float *pSum, *pSq, *pSc, *pSh, *pImgT;
    unsigned *pCnt;
    cudaGetSymbolAddress((void**)&pX0, g_X0h);
    cudaGetSymbolAddress((void**)&pY1, g_Y1h);
    cudaGetSymbolAddress((void**)&pY2, g_Y2h);
    cudaGetSymbolAddress((void**)&pY3, g_Y3h);
    cudaGetSymbolAddress((void**)&pY4, g_Y4h);
    cudaGetSymbolAddress((void**)&pW1, g_Wp1h);
    cudaGetSymbolAddress((void**)&pW2, g_Wp2h);
    cudaGetSymbolAddress((void**)&pW3, g_Wp3h);
    cudaGetSymbolAddress((void**)&pW4, g_Wp4h);
    cudaGetSymbolAddress((void**)&pSum, g_sum);
    cudaGetSymbolAddress((void**)&pSq,  g_sq);
    cudaGetSymbolAddress((void**)&pSc,  g_sc);
    cudaGetSymbolAddress((void**)&pSh,  g_sh);
    cudaGetSymbolAddress((void**)&pScH, g_scH);
    cudaGetSymbolAddress((void**)&pShH, g_shH);
    cudaGetSymbolAddress((void**)&pCnt, g_cnt);
    cudaGetSymbolAddress((void**)&pImgT, g_imgT);

    auto smemSz = [](int BM, int CIN) {
        int gemm = (BM * (CIN + 8) + 3 * 32 * (128 + 8) + 2 * CIN) * 2;
        int wrt  = (192 * 33 + 40) * 4;   // rgb writer stage
        return gemm > wrt ? gemm : wrt;
    };
    const int sm1 = smemSz(64, 96);
    const int sm2 = smemSz(128, 64);
    const int sm3 = smemSz(128, 128);

    static bool attr_done = false;
    if (!attr_done) {
        cudaFuncSetAttribute(k_gemm_h<64, 64, 96, 4, 256, false, 2>,
                             cudaFuncAttributeMaxDynamicSharedMemorySize, sm1);
        cudaFuncSetAttribute(k_gemm_h<128, 128, 64, 4, 256, true, 1>,
                             cudaFuncAttributeMaxDynamicSharedMemorySize, sm2);
        cudaFuncSetAttribute(k_gemm_h<128, 128, 128, 4, 256, true, 1>,
                             cudaFuncAttributeMaxDynamicSharedMemorySize, sm3);
        cudaFuncSetAttribute(k_gemm_h<128, 128, 128, 4, 256, true, 0>,
                             cudaFuncAttributeMaxDynamicSharedMemorySize, sm3);
        attr_done = true;
    }

    k_idx<<<B_, 256>>>(pc, npc, qv1);
    k_prep<<<32, 256>>>(w1, w2, w3, w4);
    k_tfeat<<<dim3(NPTS / 32, 2, B_), dim3(32, 32)>>>(feat);

    const int NG = B_ * PCTR;            // 4096 gather blocks
    k_gather<<<NG + 512, 256>>>(pc, npc, img1, img2, NG);

    const int GXG = MTOT / (128 * 4);    // 256 gemm blocks, 4 tiles each
    const int WB1 = 512;
    const int WB  = 256;

    // G1: 64 <- 96(pad of 67); writers: rgb1/rgb2 -> out ch [64,128) & [256,384)
    k_gemm_h<64, 64, 96, 4, 256, false, 2><<<dim3(GXG + WB1, 1), 256, sm1>>>(
        pW1, pX0, pY1, nullptr, nullptr,
        pSum + 0, pSq + 0, g1, b1, pSc + 0, pSh + 0, pScH + 0, pShH + 0, pCnt + 0,
        out, nullptr, nullptr, nullptr, pImgT, GXG, GXG, 0, 0);
    // G2: 128 <- 64, fragment-norm(L1); writers: out ch [0,64) from Y1
    k_gemm_h<128, 128, 64, 4, 256, true, 1><<<dim3(GXG + WB, 1), 256, sm2>>>(
        pW2, pY1, pY2, pScH + 0, pShH + 0,
        pSum + 256, pSq + 256, g2, b2, pSc + 256, pSh + 256, pScH + 256, pShH + 256, pCnt + 1,
        out, pY1, pSc + 0, pSh + 0, nullptr, GXG, GXG, 64, 0);
    // G3: 128 <- 128, fragment-norm(L2); writers: out ch [128,256) from Y2
    k_gemm_h<128, 128, 128, 4, 256, true, 1><<<dim3(GXG + WB, 1), 256, sm3>>>(
        pW3, pY2, pY3, pScH + 256, pShH + 256,
        pSum + 512, pSq + 512, g3, b3, pSc + 512, pSh + 512, pScH + 512, pShH + 512, pCnt + 2,
        out, pY2, pSc + 256, pSh + 256, nullptr, GXG, GXG, 128, 128);
    // G4a: ch [0,128) of layer 4, pure GEMM
    k_gemm_h<128, 128, 128, 4, 256, true, 0><<<dim3(GXG, 1), 256, sm3>>>(
        pW4, pY3, pY4, pScH + 512, pShH + 512,
        pSum + 768, pSq + 768, g4, b4, pSc + 768, pSh + 768, pScH + 768, pShH + 768, pCnt + 3,
        out, nullptr, nullptr, nullptr, nullptr, GXG, GXG, 0, 0);
    // G4b: ch [128,256) of layer 4; writers: out ch [384,512) from Y4[0..128)
    k_gemm_h<128, 128, 128, 4, 256, true, 1><<<dim3(GXG + WB, 1), 256, sm3>>>(
        pW4 + 128 * 128, pY3, pY4 + (size_t)128 * MTOT, pScH + 512, pShH + 512,
        pSum + 768 + 128, pSq + 768 + 128, g4 + 128, b4 + 128,
        pSc + 768 + 128, pSh + 768 + 128, pScH + 768 + 128, pShH + 768 + 128, pCnt + 4,
        out, pY4, pSc + 768, pSh + 768, nullptr, GXG, GXG, 128, 384);
    // out ch [512,640) from Y4[128..256)
    k_out<<<1024, 256>>>(pY4 + (size_t)128 * MTOT, 3, 128, 512, 128, out);
}

// round 15
// speedup vs baseline: 1.0230x; 1.0230x over previous
#include <cuda_runtime.h>
#include <cuda_fp16.h>
#include <math.h>

#define B_    16
#define NPTS  2048
#define PCTR  256
#define KNB   32
#define HW    1920
#define INFEA 64
#define MTOT  131072
#define EPSBN 1e-5f
#define DIST_ 0.5f
#define OUTSTRIDE 5242880   // 640*8192

// ---------------- scratch ----------------
__device__ __half g_X0h[96 * MTOT];   // channels 67..95 stay zero
__device__ __half g_Y1h[64 * MTOT];
__device__ __half g_Y2h[128 * MTOT];
__device__ __half g_Y3h[128 * MTOT];
__device__ __half g_Y4h[256 * MTOT];
__device__ float  g_imgT[B_ * HW * 192];    // pixel-major fused img1+img2
__device__ __half g_featT[B_ * NPTS * 64];  // pixel-major feat (half)
__device__ int    g_idx[MTOT];
__device__ int    g_ridx[MTOT];
__device__ float  g_vmask[B_ * PCTR];
__device__ __half g_Wp1h[64 * 96];
__device__ __half g_Wp2h[128 * 64];
__device__ __half g_Wp3h[128 * 128];
__device__ __half g_Wp4h[256 * 128];
__device__ float  g_sum[4][256];
__device__ float  g_sq[4][256];
__device__ float  g_sc[4][256];
__device__ float  g_sh[4][256];
__device__ __half g_scH[4][256];
__device__ __half g_shH[4][256];
__device__ unsigned g_cnt[6];

__device__ __forceinline__ void cp16(void* dst_smem, const void* src) {
    unsigned d = (unsigned)__cvta_generic_to_shared(dst_smem);
    asm volatile("cp.async.cg.shared.global [%0], [%1], 16;" :: "r"(d), "l"(src));
}
__device__ __forceinline__ void ldsm_x4(unsigned* r, unsigned a) {
    asm volatile("ldmatrix.sync.aligned.m8n8.x4.shared.b16 {%0,%1,%2,%3}, [%4];"
        : "=r"(r[0]), "=r"(r[1]), "=r"(r[2]), "=r"(r[3]) : "r"(a));
}
__device__ __forceinline__ void ldsm_x4_t(unsigned* r, unsigned a) {
    asm volatile("ldmatrix.sync.aligned.m8n8.x4.trans.shared.b16 {%0,%1,%2,%3}, [%4];"
        : "=r"(r[0]), "=r"(r[1]), "=r"(r[2]), "=r"(r[3]) : "r"(a));
}
__device__ __forceinline__ unsigned nrm2(unsigned v, unsigned s, unsigned t) {
    __half2 r = __hfma2(*(__half2*)&v, *(__half2*)&s, *(__half2*)&t);
    r = __hmax2(r, __half2(__half(0.f), __half(0.f)));
    return *(unsigned*)&r;
}

// ---------------- depth-ball query (+ zero stats & counters) ----------------
__global__ void k_idx(const float* __restrict__ pc,
                      const float* __restrict__ npc,
                      const int*   __restrict__ qv1)
{
    __shared__ float zs[NPTS];
    __shared__ int   stage[8][32];
    const int b   = blockIdx.x;
    const int tid = threadIdx.x;

    if (b == 0) {
        float* ps = &g_sum[0][0];
        float* pq = &g_sq[0][0];
        for (int i = tid; i < 4 * 256; i += 256) { ps[i] = 0.f; pq[i] = 0.f; }
        if (tid < 6) g_cnt[tid] = 0u;
    }
    for (int i = tid; i < NPTS; i += 256) zs[i] = pc[(b * 3 + 2) * NPTS + i];
    __syncthreads();

    const int w = tid >> 5, lane = tid & 31;
    for (int jj = 0; jj < 32; jj++) {
        const int j = w * 32 + jj;
        const float cz = npc[(b * 3 + 2) * PCTR + j];
        int cnt = 0;
        for (int c = 0; c < NPTS / 32; c++) {
            const int n = c * 32 + lane;
            const bool hit = fabsf(zs[n] - cz) < DIST_;
            const unsigned bal = __ballot_sync(0xffffffffu, hit);
            if (hit) {
                const int pos = cnt + __popc(bal & ((1u << lane) - 1u));
                if (pos < 32) stage[w][pos] = n;
            }
            cnt += __popc(bal);
            if (cnt >= 32) break;
        }
        __syncwarp();
        const int cc = min(cnt, 32);
        const int first = (cnt > 0) ? stage[w][0] : 0;
        const int v = (lane < cc) ? stage[w][lane] : first;
        const int gbase = (b * PCTR + j) * KNB;
        g_idx[gbase + lane]  = v;
        g_ridx[gbase + lane] = qv1[b * NPTS + v];
        if (lane == 0) g_vmask[b * PCTR + j] = (cnt > 0) ? 1.f : 0.f;
        __syncwarp();
    }
}

// ---------------- weight packing ----------------
__device__ __forceinline__ void packW(const float* w, __half* dst,
                                      int M, int CIN, int CINP, int tid, int nthr)
{
    const int tot = M * CINP;
    for (int i = tid; i < tot; i += nthr) {
        const int m = i / CINP, k = i - m * CINP;
        dst[i] = __float2half((k < CIN) ? w[m * CIN + k] : 0.f);
    }
}

__global__ void k_prep(const float* __restrict__ w1, const float* __restrict__ w2,
                       const float* __restrict__ w3, const float* __restrict__ w4)
{
    const int tid = blockIdx.x * blockDim.x + threadIdx.x;
    const int nthr = gridDim.x * blockDim.x;
    packW(w1, g_Wp1h, 64, 67, 96, tid, nthr);
    packW(w2, g_Wp2h, 128, 64, 64, tid, nthr);
    packW(w3, g_Wp3h, 128, 128, 128, tid, nthr);
    packW(w4, g_Wp4h, 256, 128, 128, tid, nthr);
}

// ---------------- transposes: imgs -> [B][HW][192] fp32, feat -> [B][N][64] half ----------------
__global__ void k_timg(const float* __restrict__ img1, const float* __restrict__ img2,
                       const float* __restrict__ feat)
{
    __shared__ float tile[32][33];
    const int b  = blockIdx.z;
    const int p0 = blockIdx.x * 32;
    const int yb = blockIdx.y;
    const int tx = threadIdx.x, ty = threadIdx.y;

    if (yb < 6) {           // img transpose
        if (p0 >= HW) return;
        const int c0 = yb * 32;
        const int c = c0 + ty;
        const float* src = (c < 64) ? &img1[(size_t)(b * 64 + c) * HW]
                                    : &img2[(size_t)(b * 128 + (c - 64)) * HW];
        tile[ty][tx] = src[p0 + tx];
        __syncthreads();
        g_imgT[((size_t)b * HW + p0 + ty) * 192 + c0 + tx] = tile[tx][ty];
    } else {                // feat transpose (p0 in [0,2048))
        const int c0 = (yb - 6) * 32;
        tile[ty][tx] = feat[(size_t)(b * 64 + c0 + ty) * NPTS + p0 + tx];
        __syncthreads();
        g_featT[((size_t)b * NPTS + p0 + ty) * 64 + c0 + tx] =
            __float2half(tile[tx][ty]);
    }
}

// ---------------- gather X0 (half): coalesced rows from featT ----------------
__global__ void k_gather(const float* __restrict__ pc,
                         const float* __restrict__ npc)
{
    __shared__ __align__(16) __half sm[64 * 32];
    __shared__ int    s_idx[32];
    __shared__ float  s_np[3];
    const int g = blockIdx.x;
    const int b = g >> 8;
    const int j = g & 255;
    const int t = threadIdx.x;
    const int mbase = g * KNB;

    if (t < 32) s_idx[t] = g_idx[mbase + t];
    if (t >= 32 && t < 35) s_np[t - 32] = npc[(b * 3 + (t - 32)) * PCTR + j];
    __syncthreads();

    // pc channels (3 x 32)
    if (t < 96) {
        const int c = t >> 5, k = t & 31;
        g_X0h[c * MTOT + mbase + k] =
            __float2half(pc[(b * 3 + c) * NPTS + s_idx[k]] - s_np[c]);
    }

    // feat: k = lane (32 pixels/warp), q = warp (channel chunk) -> conflict-light STS
    {
        const int k = t & 31, q = t >> 5;
        const uint4 v = *(const uint4*)&g_featT[((size_t)b * NPTS + s_idx[k]) * 64 + q * 8];
        const __half* hv = (const __half*)&v;
#pragma unroll
        for (int jj = 0; jj < 8; jj++) sm[(q * 8 + jj) * 32 + k] = hv[jj];
    }
    __syncthreads();

    // write X0 channel-major: 64 ch x 4 uint4
    {
        const int c = t >> 2, q = t & 3;
        *(uint4*)&g_X0h[(3 + c) * MTOT + mbase + q * 8] = *(uint4*)&sm[c * 32 + q * 8];
    }
}

// ---------------- multi-tile fp16 TC GEMM + embedded writer blocks ----------------
// WMODE 0: pure GEMM. WMODE 1: writers emit out = relu(wsc*wY+wsh)*vm.
// WMODE 2: writers emit rgb1/rgb2 from pixel-major imgT (coalesced).
template <int BM, int CTOT, int CIN, int TILES, int THREADS, bool NORM_IN, int WMODE>
__global__ void __launch_bounds__(THREADS)
k_gemm_h(const __half* __restrict__ Wp, const __half* __restrict__ X,
         __half* __restrict__ Y,
         const __half* __restrict__ iscH, const __half* __restrict__ ishH,
         float* __restrict__ osum, float* __restrict__ osq,
         const float* __restrict__ gam, const float* __restrict__ bet,
         float* __restrict__ sc, float* __restrict__ sh,
         __half* __restrict__ scH, __half* __restrict__ shH,
         unsigned* __restrict__ cnt,
         float* __restrict__ out,
         const __half* __restrict__ wY,
         const float* __restrict__ wsc, const float* __restrict__ wsh,
         const float* __restrict__ imgT,
         int GXG, int ngemm, int wC, int wcbase)
{
    constexpr int BN = 128, BK = 32, PIPE = 3;
    constexpr int NITER = CIN / BK;
    constexpr int TOT = TILES * NITER;
    constexpr int WROW = CIN + 8;
    constexpr int BROW = BN + 8;
    constexpr int WARPS_M = THREADS / 128;
    constexpr int WTM = BM / WARPS_M;
    constexpr int MI = WTM / 16;
    constexpr int WCH = CIN / 8;

    const int tid = threadIdx.x;
    extern __shared__ __align__(16) __half dsm[];

    // ---------- embedded writer blocks ----------
    if (WMODE != 0 && (int)blockIdx.x >= GXG) {
        const int wb  = blockIdx.x - GXG;
        const int WBn = gridDim.x - GXG;
        if (WMODE == 1) {
            const int T = wC * (MTOT / 8);
            for (int e = wb * THREADS + tid; e < T; e += WBn * THREADS) {
                const int c = e / (MTOT / 8);
                const int m = (e - c * (MTOT / 8)) * 8;
                const uint4 r = *(const uint4*)&wY[(size_t)c * MTOT + m];
                const __half* h = (const __half*)&r;
                const float s = wsc[c], t = wsh[c];
                const float vm = g_vmask[m >> 5];
                const int bb = m >> 13, rem = m & 8191;
                float* op = &out[(long)bb * OUTSTRIDE + (long)(wcbase + c) * 8192 + rem];
                *(float4*)op = make_float4(
                    fmaxf(__half2float(h[0]) * s + t, 0.f) * vm,
                    fmaxf(__half2float(h[1]) * s + t, 0.f) * vm,
                    fmaxf(__half2float(h[2]) * s + t, 0.f) * vm,
                    fmaxf(__half2float(h[3]) * s + t, 0.f) * vm);
                *(float4*)(op + 4) = make_float4(
                    fmaxf(__half2float(h[4]) * s + t, 0.f) * vm,
                    fmaxf(__half2float(h[5]) * s + t, 0.f) * vm,
                    fmaxf(__half2float(h[6]) * s + t, 0.f) * vm,
                    fmaxf(__half2float(h[7]) * s + t, 0.f) * vm);
            }
        } else {
            // rgb writer: coalesced rows from imgT, smem-staged transpose to out
            float* sm = (float*)dsm;                 // [192][33] stage
            int*   rp = (int*)(sm + 192 * 33);       // 32 pixel ids
            float* vmp = sm + 192 * 33 + 32;
            for (int g0 = wb; g0 < B_ * PCTR; g0 += WBn) {
                const int b = g0 >> 8, j = g0 & 255;
                if (tid < 32) rp[tid] = g_ridx[g0 * KNB + tid];
                if (tid == 32) vmp[0] = g_vmask[g0];
                __syncthreads();
                const float vm = vmp[0];
                for (int e = tid; e < 32 * 48; e += THREADS) {
                    const int k = e / 48, c4 = e - k * 48;
                    const float4 v =
                        ((const float4*)&imgT[((size_t)b * HW + rp[k]) * 192])[c4];
                    sm[(c4 * 4 + 0) * 33 + k] = v.x;
                    sm[(c4 * 4 + 1) * 33 + k] = v.y;
                    sm[(c4 * 4 + 2) * 33 + k] = v.z;
                    sm[(c4 * 4 + 3) * 33 + k] = v.w;
                }
                __syncthreads();
                const long ob = (long)b * OUTSTRIDE + (long)j * 32;
                for (int e = tid; e < 192 * 8; e += THREADS) {
                    const int c = e >> 3, q = e & 7;
                    const int oc = (c < 64) ? 64 + c : 192 + c;   // 256+(c-64)
                    const float* sp = &sm[c * 33 + q * 4];
                    float4 o = make_float4(sp[0] * vm, sp[1] * vm, sp[2] * vm, sp[3] * vm);
                    *(float4*)&out[ob + (long)oc * 8192 + q * 4] = o;
                }
                __syncthreads();
            }
        }
        return;
    }

    // ---------- GEMM blocks ----------
    __half* Ws = dsm;                               // BM * WROW
    __half* Bs = Ws + BM * WROW;                    // PIPE * BK * BROW
    __half* sS = Bs + PIPE * BK * BROW;             // CIN
    __half* sT = sS + CIN;                          // CIN
    __shared__ int s_last;

    const int lane = tid & 31;
    const int warp = tid >> 5;
    const int wm0  = (warp >> 2) * WTM;
    const int wn0  = (warp & 3) * 32;
    const int bn0  = blockIdx.x * (BN * TILES);
    const int bm0  = blockIdx.y * BM;
    const int grp  = lane >> 2;
    const int tig  = lane & 3;

    const unsigned ws_u = (unsigned)__cvta_generic_to_shared(Ws);
    const unsigned bs_u = (unsigned)__cvta_generic_to_shared(Bs);

    for (int f = tid; f < BM * WCH; f += THREADS) {
        const int m = f / WCH, ch = f % WCH;
        cp16(&Ws[m * WROW + ch * 8], &Wp[(size_t)(bm0 + m) * CIN + ch * 8]);
    }
    if (NORM_IN) {
        for (int e = tid; e < CIN; e += THREADS) { sS[e] = iscH[e]; sT[e] = ishH[e]; }
    }
    asm volatile("cp.async.commit_group;");

    auto cpB = [&](int g) {
        const int stg = g % PIPE;
        const int tile = g / NITER, it = g - tile * NITER;
        const int nb = bn0 + tile * BN;
        for (int e = tid; e < BK * (BN / 8); e += THREADS) {
            const int kk = e >> 4, ch = e & 15;
            cp16(&Bs[(stg * BK + kk) * BROW + ch * 8],
                 &X[(size_t)(it * BK + kk) * MTOT + nb + ch * 8]);
        }
    };
#pragma unroll
    for (int s = 0; s < PIPE - 1; s++) {
        if (s < TOT) cpB(s);
        asm volatile("cp.async.commit_group;");
    }
    asm volatile("cp.async.wait_group %0;" :: "n"(PIPE - 2));
    __syncthreads();

    float acc[MI][4][4];
#pragma unroll
    for (int mi = 0; mi < MI; mi++)
#pragma unroll
        for (int ni = 0; ni < 4; ni++)
#pragma unroll
            for (int r = 0; r < 4; r++) acc[mi][ni][r] = 0.f;

    float sSr[MI][2], sQr[MI][2];
#pragma unroll
    for (int mi = 0; mi < MI; mi++) {
        sSr[mi][0] = sSr[mi][1] = 0.f;
        sQr[mi][0] = sQr[mi][1] = 0.f;
    }

    const int a_row = (lane & 7) + ((lane >> 3) & 1) * 8;
    const int a_kq  = ((lane >> 4) & 1) * 8;
    const int b_kr  = ((lane >> 3) & 1) * 8 + (lane & 7);
    const int b_nq  = ((lane >> 4) & 1) * 8;

    for (int g = 0; g < TOT; g++) {
        const int stg = g % PIPE;
        const int tile = g / NITER, it = g - tile * NITER;
        if (g + PIPE - 1 < TOT) cpB(g + PIPE - 1);
        asm volatile("cp.async.commit_group;");

#pragma unroll
        for (int kk = 0; kk < 2; kk++) {
            const int kbase = it * BK + kk * 16;
            unsigned a[MI][4], bfr[4][2];
#pragma unroll
            for (int mi = 0; mi < MI; mi++) {
                const unsigned addr = ws_u +
                    (((wm0 + mi * 16 + a_row) * WROW) + kbase + a_kq) * 2;
                ldsm_x4(a[mi], addr);
            }
#pragma unroll
            for (int ni2 = 0; ni2 < 2; ni2++) {
                unsigned t4[4];
                const unsigned addr = bs_u + ((stg * BK + kk * 16 + b_kr) * BROW +
                                              wn0 + ni2 * 16 + b_nq) * 2;
                ldsm_x4_t(t4, addr);
                bfr[ni2 * 2][0] = t4[0]; bfr[ni2 * 2][1] = t4[1];
                bfr[ni2 * 2 + 1][0] = t4[2]; bfr[ni2 * 2 + 1][1] = t4[3];
            }
            if (NORM_IN) {
                const int k0 = kbase + 2 * tig;
                const unsigned s0 = *(const unsigned*)&sS[k0];
                const unsigned t0 = *(const unsigned*)&sT[k0];
                const unsigned s1 = *(const unsigned*)&sS[k0 + 8];
                const unsigned t1 = *(const unsigned*)&sT[k0 + 8];
#pragma unroll
                for (int ni = 0; ni < 4; ni++) {
                    bfr[ni][0] = nrm2(bfr[ni][0], s0, t0);
                    bfr[ni][1] = nrm2(bfr[ni][1], s1, t1);
                }
            }
#pragma unroll
            for (int mi = 0; mi < MI; mi++)
#pragma unroll
                for (int ni = 0; ni < 4; ni++) {
                    asm volatile(
                        "mma.sync.aligned.m16n8k16.row.col.f32.f16.f16.f32 "
                        "{%0,%1,%2,%3}, {%4,%5,%6,%7}, {%8,%9}, {%0,%1,%2,%3};"
                        : "+f"(acc[mi][ni][0]), "+f"(acc[mi][ni][1]),
                          "+f"(acc[mi][ni][2]), "+f"(acc[mi][ni][3])
                        : "r"(a[mi][0]), "r"(a[mi][1]), "r"(a[mi][2]), "r"(a[mi][3]),
                          "r"(bfr[ni][0]), "r"(bfr[ni][1]));
                }
        }

        if (it == NITER - 1) {
            const int nb = bn0 + tile * BN;
#pragma unroll
            for (int mi = 0; mi < MI; mi++) {
                const int r1 = wm0 + mi * 16 + grp;
                const int r2 = r1 + 8;
#pragma unroll
                for (int ni = 0; ni < 4; ni++) {
                    const int col = nb + wn0 + ni * 8 + tig * 2;
                    const float c0 = acc[mi][ni][0], c1 = acc[mi][ni][1];
                    const float c2 = acc[mi][ni][2], c3 = acc[mi][ni][3];
                    *(__half2*)&Y[(size_t)(bm0 + r1) * MTOT + col] = __floats2half2_rn(c0, c1);
                    *(__half2*)&Y[(size_t)(bm0 + r2) * MTOT + col] = __floats2half2_rn(c2, c3);
                    sSr[mi][0] += c0 + c1;  sQr[mi][0] += c0 * c0 + c1 * c1;
                    sSr[mi][1] += c2 + c3;  sQr[mi][1] += c2 * c2 + c3 * c3;
                    acc[mi][ni][0] = 0.f; acc[mi][ni][1] = 0.f;
                    acc[mi][ni][2] = 0.f; acc[mi][ni][3] = 0.f;
                }
            }
        }
        asm volatile("cp.async.wait_group %0;" :: "n"(PIPE - 2));
        __syncthreads();
    }

    // ---- epilogue: block stats reduction (aliases B smem) ----
    float* redS = (float*)Bs;
    float* redQ = redS + BM;
    for (int e = tid; e < BM; e += THREADS) { redS[e] = 0.f; redQ[e] = 0.f; }
    __syncthreads();
#pragma unroll
    for (int mi = 0; mi < MI; mi++) {
        const int r1 = wm0 + mi * 16 + grp;
        atomicAdd(&redS[r1], sSr[mi][0]);
        atomicAdd(&redQ[r1], sQr[mi][0]);
        atomicAdd(&redS[r1 + 8], sSr[mi][1]);
        atomicAdd(&redQ[r1 + 8], sQr[mi][1]);
    }
    __syncthreads();
    for (int e = tid; e < BM; e += THREADS) {
        atomicAdd(&osum[bm0 + e], redS[e]);
        atomicAdd(&osq[bm0 + e], redQ[e]);
    }

    // ---- last GEMM block finalizes BN scale/shift ----
    __threadfence();
    __syncthreads();
    if (tid == 0) {
        const unsigned done = atomicAdd(cnt, 1u);
        s_last = (done == (unsigned)(ngemm - 1)) ? 1 : 0;
    }
    __syncthreads();
    if (s_last) {
        __threadfence();
        for (int c = tid; c < CTOT; c += THREADS) {
            const float m = osum[c] * (1.f / (float)MTOT);
            const float v = osq[c] * (1.f / (float)MTOT) - m * m;
            const float s = gam[c] * rsqrtf(v + EPSBN);
            const float t = bet[c] - m * s;
            sc[c] = s;
            sh[c] = t;
            scH[c] = __float2half(s);
            shH[c] = __float2half(t);
        }
    }
}

// ---------------- out writer: out[cbase..cbase+C) = relu(s*Y+t)*vm (fp32) ----------------
__global__ void k_out(const __half* __restrict__ Y, int layer, int C, int cbase, int cofs,
                      float* __restrict__ out)
{
    const int T = C * (MTOT / 8);
    for (int e = blockIdx.x * blockDim.x + threadIdx.x; e < T;
         e += gridDim.x * blockDim.x) {
        const int c = e / (MTOT / 8);
        const int m = (e - c * (MTOT / 8)) * 8;
        const uint4 r = *(const uint4*)&Y[(size_t)c * MTOT + m];
        const __half* h = (const __half*)&r;
        const float s = g_sc[layer][cofs + c], t = g_sh[layer][cofs + c];
        const float vm = g_vmask[m >> 5];
        const int bb = m >> 13, rem = m & 8191;
        float* op = &out[(long)bb * OUTSTRIDE + (long)(cbase + c) * 8192 + rem];
        *(float4*)op = make_float4(
            fmaxf(__half2float(h[0]) * s + t, 0.f) * vm,
            fmaxf(__half2float(h[1]) * s + t, 0.f) * vm,
            fmaxf(__half2float(h[2]) * s + t, 0.f) * vm,
            fmaxf(__half2float(h[3]) * s + t, 0.f) * vm);
        *(float4*)(op + 4) = make_float4(
            fmaxf(__half2float(h[4]) * s + t, 0.f) * vm,
            fmaxf(__half2float(h[5]) * s + t, 0.f) * vm,
            fmaxf(__half2float(h[6]) * s + t, 0.f) * vm,
            fmaxf(__half2float(h[7]) * s + t, 0.f) * vm);
    }
}

// ---------------- launch ----------------
extern "C" void kernel_launch(void* const* d_in, const int* in_sizes, int n_in,
                              void* d_out, int out_size)
{
    const float* pc   = (const float*)d_in[0];
    const float* feat = (const float*)d_in[1];
    const float* img1 = (const float*)d_in[2];
    const float* img2 = (const float*)d_in[3];
    const int*   qv1  = (const int*)d_in[5];
    const float* npc  = (const float*)d_in[6];
    const float* w1 = (const float*)d_in[7];
    const float* g1 = (const float*)d_in[8];
    const float* b1 = (const float*)d_in[9];
    const float* w2 = (const float*)d_in[10];
    const float* g2 = (const float*)d_in[11];
    const float* b2 = (const float*)d_in[12];
    const float* w3 = (const float*)d_in[13];
    const float* g3 = (const float*)d_in[14];
    const float* b3 = (const float*)d_in[15];
    const float* w4 = (const float*)d_in[16];
    const float* g4 = (const float*)d_in[17];
    const float* b4 = (const float*)d_in[18];
    float* out = (float*)d_out;

    __half *pX0, *pY1, *pY2, *pY3, *pY4;
    __half *pW1, *pW2, *pW3, *pW4, *pScH, *pShH;
    float *pSum, *pSq, *pSc, *pSh, *pImgT;
    unsigned *pCnt;
    cudaGetSymbolAddress((void**)&pX0, g_X0h);
    cudaGetSymbolAddress((void**)&pY1, g_Y1h);
    cudaGetSymbolAddress((void**)&pY2, g_Y2h);
    cudaGetSymbolAddress((void**)&pY3, g_Y3h);
    cudaGetSymbolAddress((void**)&pY4, g_Y4h);
    cudaGetSymbolAddress((void**)&pW1, g_Wp1h);
    cudaGetSymbolAddress((void**)&pW2, g_Wp2h);
    cudaGetSymbolAddress((void**)&pW3, g_Wp3h);
    cudaGetSymbolAddress((void**)&pW4, g_Wp4h);
    cudaGetSymbolAddress((void**)&pSum, g_sum);
    cudaGetSymbolAddress((void**)&pSq,  g_sq);
    cudaGetSymbolAddress((void**)&pSc,  g_sc);
    cudaGetSymbolAddress((void**)&pSh,  g_sh);
    cudaGetSymbolAddress((void**)&pScH, g_scH);
    cudaGetSymbolAddress((void**)&pShH, g_shH);
    cudaGetSymbolAddress((void**)&pCnt, g_cnt);
    cudaGetSymbolAddress((void**)&pImgT, g_imgT);

    auto smemSz = [](int BM, int CIN) {
        int gemm = (BM * (CIN + 8) + 3 * 32 * (128 + 8) + 2 * CIN) * 2;
        int wrt  = (192 * 33 + 40) * 4;   // rgb writer stage
        return gemm > wrt ? gemm : wrt;
    };
    const int sm1 = smemSz(64, 96);
    const int sm2 = smemSz(128, 64);
    const int sm3 = smemSz(128, 128);

    static bool attr_done = false;
    if (!attr_done) {
        cudaFuncSetAttribute(k_gemm_h<64, 64, 96, 4, 256, false, 2>,
                             cudaFuncAttributeMaxDynamicSharedMemorySize, sm1);
        cudaFuncSetAttribute(k_gemm_h<128, 128, 64, 4, 256, true, 1>,
                             cudaFuncAttributeMaxDynamicSharedMemorySize, sm2);
        cudaFuncSetAttribute(k_gemm_h<128, 128, 128, 4, 256, true, 1>,
                             cudaFuncAttributeMaxDynamicSharedMemorySize, sm3);
        cudaFuncSetAttribute(k_gemm_h<128, 128, 128, 4, 256, true, 0>,
                             cudaFuncAttributeMaxDynamicSharedMemorySize, sm3);
        attr_done = true;
    }

    k_idx<<<B_, 256>>>(pc, npc, qv1);
    k_prep<<<32, 256>>>(w1, w2, w3, w4);
    // img transpose (y=0..5) + feat transpose (y=6..7)
    k_timg<<<dim3(64, 8, B_), dim3(32, 32)>>>(img1, img2, feat);
    k_gather<<<B_ * PCTR, 256>>>(pc, npc);

    const int GXG = MTOT / (128 * 4);    // 256 gemm blocks, 4 tiles each
    const int WB1 = 512;
    const int WB  = 256;

    // G1: 64 <- 96(pad of 67); writers: rgb1/rgb2 -> out ch [64,128) & [256,384)
    k_gemm_h<64, 64, 96, 4, 256, false, 2><<<dim3(GXG + WB1, 1), 256, sm1>>>(
        pW1, pX0, pY1, nullptr, nullptr,
        pSum + 0, pSq + 0, g1, b1, pSc + 0, pSh + 0, pScH + 0, pShH + 0, pCnt + 0,
        out, nullptr, nullptr, nullptr, pImgT, GXG, GXG, 0, 0);
    // G2: 128 <- 64, fragment-norm(L1); writers: out ch [0,64) from Y1
    k_gemm_h<128, 128, 64, 4, 256, true, 1><<<dim3(GXG + WB, 1), 256, sm2>>>(
        pW2, pY1, pY2, pScH + 0, pShH + 0,
        pSum + 256, pSq + 256, g2, b2, pSc + 256, pSh + 256, pScH + 256, pShH + 256, pCnt + 1,
        out, pY1, pSc + 0, pSh + 0, nullptr, GXG, GXG, 64, 0);
    // G3: 128 <- 128, fragment-norm(L2); writers: out ch [128,256) from Y2
    k_gemm_h<128, 128, 128, 4, 256, true, 1><<<dim3(GXG + WB, 1), 256, sm3>>>(
        pW3, pY2, pY3, pScH + 256, pShH + 256,
        pSum + 512, pSq + 512, g3, b3, pSc + 512, pSh + 512, pScH + 512, pShH + 512, pCnt + 2,
        out, pY2, pSc + 256, pSh + 256, nullptr, GXG, GXG, 128, 128);
    // G4a: ch [0,128) of layer 4, pure GEMM
    k_gemm_h<128, 128, 128, 4, 256, true, 0><<<dim3(GXG, 1), 256, sm3>>>(
        pW4, pY3, pY4, pScH + 512, pShH + 512,
        pSum + 768, pSq + 768, g4, b4, pSc + 768, pSh + 768, pScH + 768, pShH + 768, pCnt + 3,
        out, nullptr, nullptr, nullptr, nullptr, GXG, GXG, 0, 0);
    // G4b: ch [128,256) of layer 4; writers: out ch [384,512) from Y4[0..128)
    k_gemm_h<128, 128, 128, 4, 256, true, 1><<<dim3(GXG + WB, 1), 256, sm3>>>(
        pW4 + 128 * 128, pY3, pY4 + (size_t)128 * MTOT, pScH + 512, pShH + 512,
        pSum + 768 + 128, pSq + 768 + 128, g4 + 128, b4 + 128,
        pSc + 768 + 128, pSh + 768 + 128, pScH + 768 + 128, pShH + 768 + 128, pCnt + 4,
        out, pY4, pSc + 768, pSh + 768, nullptr, GXG, GXG, 128, 384);
    // out ch [512,640) from Y4[128..256)
    k_out<<<1024, 256>>>(pY4 + (size_t)128 * MTOT, 3, 128, 512, 128, out);
}

// round 16
// speedup vs baseline: 1.0355x; 1.0122x over previous
#include <cuda_runtime.h>
#include <cuda_fp16.h>
#include <math.h>

#define B_    16
#define NPTS  2048
#define PCTR  256
#define KNB   32
#define HW    1920
#define INFEA 64
#define MTOT  131072
#define EPSBN 1e-5f
#define DIST_ 0.5f
#define OUTSTRIDE 5242880   // 640*8192

// ---------------- scratch ----------------
__device__ __half g_X0h[96 * MTOT];   // channels 67..95 stay zero
__device__ __half g_Y1h[64 * MTOT];
__device__ __half g_Y2h[128 * MTOT];
__device__ __half g_Y3h[128 * MTOT];
__device__ __half g_Y4h[256 * MTOT];
__device__ float  g_imgT[B_ * HW * 192];    // pixel-major fused img1+img2
__device__ __half g_featT[B_ * NPTS * 64];  // pixel-major feat (half)
__device__ int    g_idx[MTOT];
__device__ int    g_ridx[MTOT];
__device__ float  g_vmask[B_ * PCTR];
__device__ __half g_Wp1h[64 * 96];
__device__ __half g_Wp2h[128 * 64];
__device__ __half g_Wp3h[128 * 128];
__device__ __half g_Wp4h[256 * 128];
__device__ float  g_sum[4][256];
__device__ float  g_sq[4][256];
__device__ float  g_sc[4][256];
__device__ float  g_sh[4][256];
__device__ __half g_scH[4][256];
__device__ __half g_shH[4][256];
__device__ unsigned g_cnt[4];

__device__ __forceinline__ void cp16(void* dst_smem, const void* src) {
    unsigned d = (unsigned)__cvta_generic_to_shared(dst_smem);
    asm volatile("cp.async.cg.shared.global [%0], [%1], 16;" :: "r"(d), "l"(src));
}
__device__ __forceinline__ void ldsm_x4(unsigned* r, unsigned a) {
    asm volatile("ldmatrix.sync.aligned.m8n8.x4.shared.b16 {%0,%1,%2,%3}, [%4];"
        : "=r"(r[0]), "=r"(r[1]), "=r"(r[2]), "=r"(r[3]) : "r"(a));
}
__device__ __forceinline__ void ldsm_x4_t(unsigned* r, unsigned a) {
    asm volatile("ldmatrix.sync.aligned.m8n8.x4.trans.shared.b16 {%0,%1,%2,%3}, [%4];"
        : "=r"(r[0]), "=r"(r[1]), "=r"(r[2]), "=r"(r[3]) : "r"(a));
}
__device__ __forceinline__ unsigned nrm2(unsigned v, unsigned s, unsigned t) {
    __half2 r = __hfma2(*(__half2*)&v, *(__half2*)&s, *(__half2*)&t);
    r = __hmax2(r, __half2(__half(0.f), __half(0.f)));
    return *(unsigned*)&r;
}

// ---------------- depth-ball query (+ zero stats & counters) ----------------
__global__ void k_idx(const float* __restrict__ pc,
                      const float* __restrict__ npc,
                      const int*   __restrict__ qv1)
{
    __shared__ float zs[NPTS];
    __shared__ int   stage[8][32];
    const int b   = blockIdx.x;
    const int tid = threadIdx.x;

    if (b == 0) {
        float* ps = &g_sum[0][0];
        float* pq = &g_sq[0][0];
        for (int i = tid; i < 4 * 256; i += 256) { ps[i] = 0.f; pq[i] = 0.f; }
        if (tid < 4) g_cnt[tid] = 0u;
    }
    for (int i = tid; i < NPTS; i += 256) zs[i] = pc[(b * 3 + 2) * NPTS + i];
    __syncthreads();

    const int w = tid >> 5, lane = tid & 31;
    for (int jj = 0; jj < 32; jj++) {
        const int j = w * 32 + jj;
        const float cz = npc[(b * 3 + 2) * PCTR + j];
        int cnt = 0;
        for (int c = 0; c < NPTS / 32; c++) {
            const int n = c * 32 + lane;
            const bool hit = fabsf(zs[n] - cz) < DIST_;
            const unsigned bal = __ballot_sync(0xffffffffu, hit);
            if (hit) {
                const int pos = cnt + __popc(bal & ((1u << lane) - 1u));
                if (pos < 32) stage[w][pos] = n;
            }
            cnt += __popc(bal);
            if (cnt >= 32) break;
        }
        __syncwarp();
        const int cc = min(cnt, 32);
        const int first = (cnt > 0) ? stage[w][0] : 0;
        const int v = (lane < cc) ? stage[w][lane] : first;
        const int gbase = (b * PCTR + j) * KNB;
        g_idx[gbase + lane]  = v;
        g_ridx[gbase + lane] = qv1[b * NPTS + v];
        if (lane == 0) g_vmask[b * PCTR + j] = (cnt > 0) ? 1.f : 0.f;
        __syncwarp();
    }
}

// ---------------- weight packing ----------------
__device__ __forceinline__ void packW(const float* w, __half* dst,
                                      int M, int CIN, int CINP, int tid, int nthr)
{
    const int tot = M * CINP;
    for (int i = tid; i < tot; i += nthr) {
        const int m = i / CINP, k = i - m * CINP;
        dst[i] = __float2half((k < CIN) ? w[m * CIN + k] : 0.f);
    }
}

__global__ void k_prep(const float* __restrict__ w1, const float* __restrict__ w2,
                       const float* __restrict__ w3, const float* __restrict__ w4)
{
    const int tid = blockIdx.x * blockDim.x + threadIdx.x;
    const int nthr = gridDim.x * blockDim.x;
    packW(w1, g_Wp1h, 64, 67, 96, tid, nthr);
    packW(w2, g_Wp2h, 128, 64, 64, tid, nthr);
    packW(w3, g_Wp3h, 128, 128, 128, tid, nthr);
    packW(w4, g_Wp4h, 256, 128, 128, tid, nthr);
}

// ---------------- transposes: imgs -> [B][HW][192] fp32, feat -> [B][N][64] half ----------------
__global__ void k_timg(const float* __restrict__ img1, const float* __restrict__ img2,
                       const float* __restrict__ feat)
{
    __shared__ float tile[32][33];
    const int b  = blockIdx.z;
    const int p0 = blockIdx.x * 32;
    const int yb = blockIdx.y;
    const int tx = threadIdx.x, ty = threadIdx.y;

    if (yb < 6) {           // img transpose
        if (p0 >= HW) return;
        const int c0 = yb * 32;
        const int c = c0 + ty;
        const float* src = (c < 64) ? &img1[(size_t)(b * 64 + c) * HW]
                                    : &img2[(size_t)(b * 128 + (c - 64)) * HW];
        tile[ty][tx] = src[p0 + tx];
        __syncthreads();
        g_imgT[((size_t)b * HW + p0 + ty) * 192 + c0 + tx] = tile[tx][ty];
    } else {                // feat transpose (p0 in [0,2048))
        const int c0 = (yb - 6) * 32;
        tile[ty][tx] = feat[(size_t)(b * 64 + c0 + ty) * NPTS + p0 + tx];
        __syncthreads();
        g_featT[((size_t)b * NPTS + p0 + ty) * 64 + c0 + tx] =
            __float2half(tile[tx][ty]);
    }
}

// ---------------- gather X0 (half): coalesced rows from featT ----------------
__global__ void k_gather(const float* __restrict__ pc,
                         const float* __restrict__ npc)
{
    __shared__ __align__(16) __half sm[64 * 32];
    __shared__ int    s_idx[32];
    __shared__ float  s_np[3];
    const int g = blockIdx.x;
    const int b = g >> 8;
    const int j = g & 255;
    const int t = threadIdx.x;
    const int mbase = g * KNB;

    if (t < 32) s_idx[t] = g_idx[mbase + t];
    if (t >= 32 && t < 35) s_np[t - 32] = npc[(b * 3 + (t - 32)) * PCTR + j];
    __syncthreads();

    // pc channels (3 x 32)
    if (t < 96) {
        const int c = t >> 5, k = t & 31;
        g_X0h[c * MTOT + mbase + k] =
            __float2half(pc[(b * 3 + c) * NPTS + s_idx[k]] - s_np[c]);
    }

    // feat: k = lane (32 pixels/warp), q = warp (channel chunk) -> conflict-light STS
    {
        const int k = t & 31, q = t >> 5;
        const uint4 v = *(const uint4*)&g_featT[((size_t)b * NPTS + s_idx[k]) * 64 + q * 8];
        const __half* hv = (const __half*)&v;
#pragma unroll
        for (int jj = 0; jj < 8; jj++) sm[(q * 8 + jj) * 32 + k] = hv[jj];
    }
    __syncthreads();

    // write X0 channel-major: 64 ch x 4 uint4
    {
        const int c = t >> 2, q = t & 3;
        *(uint4*)&g_X0h[(3 + c) * MTOT + mbase + q * 8] = *(uint4*)&sm[c * 32 + q * 8];
    }
}

// ---------------- multi-tile fp16 TC GEMM + embedded writer blocks ----------------
// WMODE 0: pure GEMM. WMODE 1: writers emit out = relu(wsc*wY+wsh)*vm.
// WMODE 2: writers emit rgb1/rgb2 from pixel-major imgT (coalesced).
template <int BM, int CTOT, int CIN, int TILES, int THREADS, bool NORM_IN, int WMODE>
__global__ void __launch_bounds__(THREADS)
k_gemm_h(const __half* __restrict__ Wp, const __half* __restrict__ X,
         __half* __restrict__ Y,
         const __half* __restrict__ iscH, const __half* __restrict__ ishH,
         float* __restrict__ osum, float* __restrict__ osq,
         const float* __restrict__ gam, const float* __restrict__ bet,
         float* __restrict__ sc, float* __restrict__ sh,
         __half* __restrict__ scH, __half* __restrict__ shH,
         unsigned* __restrict__ cnt,
         float* __restrict__ out,
         const __half* __restrict__ wY,
         const float* __restrict__ wsc, const float* __restrict__ wsh,
         const float* __restrict__ imgT,
         int GXG, int ngemm, int wC, int wcbase)
{
    constexpr int BN = 128, BK = 32, PIPE = 3;
    constexpr int NITER = CIN / BK;
    constexpr int TOT = TILES * NITER;
    constexpr int WROW = CIN + 8;
    constexpr int BROW = BN + 8;
    constexpr int WARPS_M = THREADS / 128;
    constexpr int WTM = BM / WARPS_M;
    constexpr int MI = WTM / 16;
    constexpr int WCH = CIN / 8;

    const int tid = threadIdx.x;
    extern __shared__ __align__(16) __half dsm[];

    // ---------- embedded writer blocks ----------
    if (WMODE != 0 && (int)blockIdx.x >= GXG) {
        const int wb  = blockIdx.x - GXG;
        const int WBn = gridDim.x - GXG;
        if (WMODE == 1) {
            const int T = wC * (MTOT / 8);
            for (int e = wb * THREADS + tid; e < T; e += WBn * THREADS) {
                const int c = e / (MTOT / 8);
                const int m = (e - c * (MTOT / 8)) * 8;
                const uint4 r = *(const uint4*)&wY[(size_t)c * MTOT + m];
                const __half* h = (const __half*)&r;
                const float s = wsc[c], t = wsh[c];
                const float vm = g_vmask[m >> 5];
                const int bb = m >> 13, rem = m & 8191;
                float* op = &out[(long)bb * OUTSTRIDE + (long)(wcbase + c) * 8192 + rem];
                *(float4*)op = make_float4(
                    fmaxf(__half2float(h[0]) * s + t, 0.f) * vm,
                    fmaxf(__half2float(h[1]) * s + t, 0.f) * vm,
                    fmaxf(__half2float(h[2]) * s + t, 0.f) * vm,
                    fmaxf(__half2float(h[3]) * s + t, 0.f) * vm);
                *(float4*)(op + 4) = make_float4(
                    fmaxf(__half2float(h[4]) * s + t, 0.f) * vm,
                    fmaxf(__half2float(h[5]) * s + t, 0.f) * vm,
                    fmaxf(__half2float(h[6]) * s + t, 0.f) * vm,
                    fmaxf(__half2float(h[7]) * s + t, 0.f) * vm);
            }
        } else {
            // rgb writer: coalesced rows from imgT, smem-staged transpose to out
            float* sm = (float*)dsm;                 // [192][33] stage
            int*   rp = (int*)(sm + 192 * 33);       // 32 pixel ids
            float* vmp = sm + 192 * 33 + 32;
            for (int g0 = wb; g0 < B_ * PCTR; g0 += WBn) {
                const int b = g0 >> 8, j = g0 & 255;
                if (tid < 32) rp[tid] = g_ridx[g0 * KNB + tid];
                if (tid == 32) vmp[0] = g_vmask[g0];
                __syncthreads();
                const float vm = vmp[0];
                for (int e = tid; e < 32 * 48; e += THREADS) {
                    const int k = e / 48, c4 = e - k * 48;
                    const float4 v =
                        ((const float4*)&imgT[((size_t)b * HW + rp[k]) * 192])[c4];
                    sm[(c4 * 4 + 0) * 33 + k] = v.x;
                    sm[(c4 * 4 + 1) * 33 + k] = v.y;
                    sm[(c4 * 4 + 2) * 33 + k] = v.z;
                    sm[(c4 * 4 + 3) * 33 + k] = v.w;
                }
                __syncthreads();
                const long ob = (long)b * OUTSTRIDE + (long)j * 32;
                for (int e = tid; e < 192 * 8; e += THREADS) {
                    const int c = e >> 3, q = e & 7;
                    const int oc = (c < 64) ? 64 + c : 192 + c;   // 256+(c-64)
                    const float* sp = &sm[c * 33 + q * 4];
                    float4 o = make_float4(sp[0] * vm, sp[1] * vm, sp[2] * vm, sp[3] * vm);
                    *(float4*)&out[ob + (long)oc * 8192 + q * 4] = o;
                }
                __syncthreads();
            }
        }
        return;
    }

    // ---------- GEMM blocks ----------
    __half* Ws = dsm;                               // BM * WROW
    __half* Bs = Ws + BM * WROW;                    // PIPE * BK * BROW
    __half* sS = Bs + PIPE * BK * BROW;             // CIN
    __half* sT = sS + CIN;                          // CIN
    __shared__ int s_last;

    const int lane = tid & 31;
    const int warp = tid >> 5;
    const int wm0  = (warp >> 2) * WTM;
    const int wn0  = (warp & 3) * 32;
    const int bn0  = blockIdx.x * (BN * TILES);
    const int bm0  = blockIdx.y * BM;
    const int grp  = lane >> 2;
    const int tig  = lane & 3;

    const unsigned ws_u = (unsigned)__cvta_generic_to_shared(Ws);
    const unsigned bs_u = (unsigned)__cvta_generic_to_shared(Bs);

    for (int f = tid; f < BM * WCH; f += THREADS) {
        const int m = f / WCH, ch = f % WCH;
        cp16(&Ws[m * WROW + ch * 8], &Wp[(size_t)(bm0 + m) * CIN + ch * 8]);
    }
    if (NORM_IN) {
        for (int e = tid; e < CIN; e += THREADS) { sS[e] = iscH[e]; sT[e] = ishH[e]; }
    }
    asm volatile("cp.async.commit_group;");

    auto cpB = [&](int g) {
        const int stg = g % PIPE;
        const int tile = g / NITER, it = g - tile * NITER;
        const int nb = bn0 + tile * BN;
        for (int e = tid; e < BK * (BN / 8); e += THREADS) {
            const int kk = e >> 4, ch = e & 15;
            cp16(&Bs[(stg * BK + kk) * BROW + ch * 8],
                 &X[(size_t)(it * BK + kk) * MTOT + nb + ch * 8]);
        }
    };
#pragma unroll
    for (int s = 0; s < PIPE - 1; s++) {
        if (s < TOT) cpB(s);
        asm volatile("cp.async.commit_group;");
    }
    asm volatile("cp.async.wait_group %0;" :: "n"(PIPE - 2));
    __syncthreads();

    float acc[MI][4][4];
#pragma unroll
    for (int mi = 0; mi < MI; mi++)
#pragma unroll
        for (int ni = 0; ni < 4; ni++)
#pragma unroll
            for (int r = 0; r < 4; r++) acc[mi][ni][r] = 0.f;

    float sSr[MI][2], sQr[MI][2];
#pragma unroll
    for (int mi = 0; mi < MI; mi++) {
        sSr[mi][0] = sSr[mi][1] = 0.f;
        sQr[mi][0] = sQr[mi][1] = 0.f;
    }

    const int a_row = (lane & 7) + ((lane >> 3) & 1) * 8;
    const int a_kq  = ((lane >> 4) & 1) * 8;
    const int b_kr  = ((lane >> 3) & 1) * 8 + (lane & 7);
    const int b_nq  = ((lane >> 4) & 1) * 8;

    for (int g = 0; g < TOT; g++) {
        const int stg = g % PIPE;
        const int tile = g / NITER, it = g - tile * NITER;
        if (g + PIPE - 1 < TOT) cpB(g + PIPE - 1);
        asm volatile("cp.async.commit_group;");

#pragma unroll
        for (int kk = 0; kk < 2; kk++) {
            const int kbase = it * BK + kk * 16;
            unsigned a[MI][4], bfr[4][2];
#pragma unroll
            for (int mi = 0; mi < MI; mi++) {
                const unsigned addr = ws_u +
                    (((wm0 + mi * 16 + a_row) * WROW) + kbase + a_kq) * 2;
                ldsm_x4(a[mi], addr);
            }
#pragma unroll
            for (int ni2 = 0; ni2 < 2; ni2++) {
                unsigned t4[4];
                const unsigned addr = bs_u + ((stg * BK + kk * 16 + b_kr) * BROW +
                                              wn0 + ni2 * 16 + b_nq) * 2;
                ldsm_x4_t(t4, addr);
                bfr[ni2 * 2][0] = t4[0]; bfr[ni2 * 2][1] = t4[1];
                bfr[ni2 * 2 + 1][0] = t4[2]; bfr[ni2 * 2 + 1][1] = t4[3];
            }
            if (NORM_IN) {
                const int k0 = kbase + 2 * tig;
                const unsigned s0 = *(const unsigned*)&sS[k0];
                const unsigned t0 = *(const unsigned*)&sT[k0];
                const unsigned s1 = *(const unsigned*)&sS[k0 + 8];
                const unsigned t1 = *(const unsigned*)&sT[k0 + 8];
#pragma unroll
                for (int ni = 0; ni < 4; ni++) {
                    bfr[ni][0] = nrm2(bfr[ni][0], s0, t0);
                    bfr[ni][1] = nrm2(bfr[ni][1], s1, t1);
                }
            }
#pragma unroll
            for (int mi = 0; mi < MI; mi++)
#pragma unroll
                for (int ni = 0; ni < 4; ni++) {
                    asm volatile(
                        "mma.sync.aligned.m16n8k16.row.col.f32.f16.f16.f32 "
                        "{%0,%1,%2,%3}, {%4,%5,%6,%7}, {%8,%9}, {%0,%1,%2,%3};"
                        : "+f"(acc[mi][ni][0]), "+f"(acc[mi][ni][1]),
                          "+f"(acc[mi][ni][2]), "+f"(acc[mi][ni][3])
                        : "r"(a[mi][0]), "r"(a[mi][1]), "r"(a[mi][2]), "r"(a[mi][3]),
                          "r"(bfr[ni][0]), "r"(bfr[ni][1]));
                }
        }

        if (it == NITER - 1) {
            const int nb = bn0 + tile * BN;
#pragma unroll
            for (int mi = 0; mi < MI; mi++) {
                const int r1 = wm0 + mi * 16 + grp;
                const int r2 = r1 + 8;
#pragma unroll
                for (int ni = 0; ni < 4; ni++) {
                    const int col = nb + wn0 + ni * 8 + tig * 2;
                    const float c0 = acc[mi][ni][0], c1 = acc[mi][ni][1];
                    const float c2 = acc[mi][ni][2], c3 = acc[mi][ni][3];
                    *(__half2*)&Y[(size_t)(bm0 + r1) * MTOT + col] = __floats2half2_rn(c0, c1);
                    *(__half2*)&Y[(size_t)(bm0 + r2) * MTOT + col] = __floats2half2_rn(c2, c3);
                    sSr[mi][0] += c0 + c1;  sQr[mi][0] += c0 * c0 + c1 * c1;
                    sSr[mi][1] += c2 + c3;  sQr[mi][1] += c2 * c2 + c3 * c3;
                    acc[mi][ni][0] = 0.f; acc[mi][ni][1] = 0.f;
                    acc[mi][ni][2] = 0.f; acc[mi][ni][3] = 0.f;
                }
            }
        }
        asm volatile("cp.async.wait_group %0;" :: "n"(PIPE - 2));
        __syncthreads();
    }

    // ---- epilogue: block stats reduction (aliases B smem) ----
    float* redS = (float*)Bs;
    float* redQ = redS + BM;
    for (int e = tid; e < BM; e += THREADS) { redS[e] = 0.f; redQ[e] = 0.f; }
    __syncthreads();
#pragma unroll
    for (int mi = 0; mi < MI; mi++) {
        const int r1 = wm0 + mi * 16 + grp;
        atomicAdd(&redS[r1], sSr[mi][0]);
        atomicAdd(&redQ[r1], sQr[mi][0]);
        atomicAdd(&redS[r1 + 8], sSr[mi][1]);
        atomicAdd(&redQ[r1 + 8], sQr[mi][1]);
    }
    __syncthreads();
    for (int e = tid; e < BM; e += THREADS) {
        atomicAdd(&osum[bm0 + e], redS[e]);
        atomicAdd(&osq[bm0 + e], redQ[e]);
    }

    // ---- last GEMM block finalizes BN scale/shift ----
    __threadfence();
    __syncthreads();
    if (tid == 0) {
        const unsigned done = atomicAdd(cnt, 1u);
        s_last = (done == (unsigned)(ngemm - 1)) ? 1 : 0;
    }
    __syncthreads();
    if (s_last) {
        __threadfence();
        for (int c = tid; c < CTOT; c += THREADS) {
            const float m = osum[c] * (1.f / (float)MTOT);
            const float v = osq[c] * (1.f / (float)MTOT) - m * m;
            const float s = gam[c] * rsqrtf(v + EPSBN);
            const float t = bet[c] - m * s;
            sc[c] = s;
            sh[c] = t;
            scH[c] = __float2half(s);
            shH[c] = __float2half(t);
        }
    }
}

// ---------------- out writer: out[cbase..cbase+C) = relu(s*Y+t)*vm (fp32) ----------------
__global__ void k_out(const __half* __restrict__ Y, int layer, int C, int cbase,
                      float* __restrict__ out)
{
    const int T = C * (MTOT / 8);
    for (int e = blockIdx.x * blockDim.x + threadIdx.x; e < T;
         e += gridDim.x * blockDim.x) {
        const int c = e / (MTOT / 8);
        const int m = (e - c * (MTOT / 8)) * 8;
        const uint4 r = *(const uint4*)&Y[(size_t)c * MTOT + m];
        const __half* h = (const __half*)&r;
        const float s = g_sc[layer][c], t = g_sh[layer][c];
        const float vm = g_vmask[m >> 5];
        const int bb = m >> 13, rem = m & 8191;
        float* op = &out[(long)bb * OUTSTRIDE + (long)(cbase + c) * 8192 + rem];
        *(float4*)op = make_float4(
            fmaxf(__half2float(h[0]) * s + t, 0.f) * vm,
            fmaxf(__half2float(h[1]) * s + t, 0.f) * vm,
            fmaxf(__half2float(h[2]) * s + t, 0.f) * vm,
            fmaxf(__half2float(h[3]) * s + t, 0.f) * vm);
        *(float4*)(op + 4) = make_float4(
            fmaxf(__half2float(h[4]) * s + t, 0.f) * vm,
            fmaxf(__half2float(h[5]) * s + t, 0.f) * vm,
            fmaxf(__half2float(h[6]) * s + t, 0.f) * vm,
            fmaxf(__half2float(h[7]) * s + t, 0.f) * vm);
    }
}

// ---------------- launch ----------------
extern "C" void kernel_launch(void* const* d_in, const int* in_sizes, int n_in,
                              void* d_out, int out_size)
{
    const float* pc   = (const float*)d_in[0];
    const float* feat = (const float*)d_in[1];
    const float* img1 = (const float*)d_in[2];
    const float* img2 = (const float*)d_in[3];
    const int*   qv1  = (const int*)d_in[5];
    const float* npc  = (const float*)d_in[6];
    const float* w1 = (const float*)d_in[7];
    const float* g1 = (const float*)d_in[8];
    const float* b1 = (const float*)d_in[9];
    const float* w2 = (const float*)d_in[10];
    const float* g2 = (const float*)d_in[11];
    const float* b2 = (const float*)d_in[12];
    const float* w3 = (const float*)d_in[13];
    const float* g3 = (const float*)d_in[14];
    const float* b3 = (const float*)d_in[15];
    const float* w4 = (const float*)d_in[16];
    const float* g4 = (const float*)d_in[17];
    const float* b4 = (const float*)d_in[18];
    float* out = (float*)d_out;

    __half *pX0, *pY1, *pY2, *pY3, *pY4;
    __half *pW1, *pW2, *pW3, *pW4, *pScH, *pShH;
    float *pSum, *pSq, *pSc, *pSh, *pImgT;
    unsigned *pCnt;
    cudaGetSymbolAddress((void**)&pX0, g_X0h);
    cudaGetSymbolAddress((void**)&pY1, g_Y1h);
    cudaGetSymbolAddress((void**)&pY2, g_Y2h);
    cudaGetSymbolAddress((void**)&pY3, g_Y3h);
    cudaGetSymbolAddress((void**)&pY4, g_Y4h);
    cudaGetSymbolAddress((void**)&pW1, g_Wp1h);
    cudaGetSymbolAddress((void**)&pW2, g_Wp2h);
    cudaGetSymbolAddress((void**)&pW3, g_Wp3h);
    cudaGetSymbolAddress((void**)&pW4, g_Wp4h);
    cudaGetSymbolAddress((void**)&pSum, g_sum);
    cudaGetSymbolAddress((void**)&pSq,  g_sq);
    cudaGetSymbolAddress((void**)&pSc,  g_sc);
    cudaGetSymbolAddress((void**)&pSh,  g_sh);
    cudaGetSymbolAddress((void**)&pScH, g_scH);
    cudaGetSymbolAddress((void**)&pShH, g_shH);
    cudaGetSymbolAddress((void**)&pCnt, g_cnt);
    cudaGetSymbolAddress((void**)&pImgT, g_imgT);

    auto smemSz = [](int BM, int CIN) {
        int gemm = (BM * (CIN + 8) + 3 * 32 * (128 + 8) + 2 * CIN) * 2;
        int wrt  = (192 * 33 + 40) * 4;   // rgb writer stage
        return gemm > wrt ? gemm : wrt;
    };
    const int sm1 = smemSz(64, 96);
    const int sm2 = smemSz(128, 64);
    const int sm3 = smemSz(128, 128);

    static bool attr_done = false;
    if (!attr_done) {
        cudaFuncSetAttribute(k_gemm_h<64, 64, 96, 4, 256, false, 2>,
                             cudaFuncAttributeMaxDynamicSharedMemorySize, sm1);
        cudaFuncSetAttribute(k_gemm_h<128, 128, 64, 4, 256, true, 1>,
                             cudaFuncAttributeMaxDynamicSharedMemorySize, sm2);
        cudaFuncSetAttribute(k_gemm_h<128, 128, 128, 4, 256, true, 1>,
                             cudaFuncAttributeMaxDynamicSharedMemorySize, sm3);
        cudaFuncSetAttribute(k_gemm_h<128, 256, 128, 4, 256, true, 0>,
                             cudaFuncAttributeMaxDynamicSharedMemorySize, sm3);
        attr_done = true;
    }

    k_idx<<<B_, 256>>>(pc, npc, qv1);
    k_prep<<<32, 256>>>(w1, w2, w3, w4);
    // img transpose (y=0..5) + feat transpose (y=6..7)
    k_timg<<<dim3(64, 8, B_), dim3(32, 32)>>>(img1, img2, feat);
    k_gather<<<B_ * PCTR, 256>>>(pc, npc);

    const int GXG = MTOT / (128 * 4);    // 256 gemm blocks, 4 tiles each
    const int WB1 = 512;
    const int WB  = 256;

    // G1: 64 <- 96(pad of 67); writers: rgb1/rgb2 -> out ch [64,128) & [256,384)
    k_gemm_h<64, 64, 96, 4, 256, false, 2><<<dim3(GXG + WB1, 1), 256, sm1>>>(
        pW1, pX0, pY1, nullptr, nullptr,
        pSum + 0, pSq + 0, g1, b1, pSc + 0, pSh + 0, pScH + 0, pShH + 0, pCnt + 0,
        out, nullptr, nullptr, nullptr, pImgT, GXG, GXG, 0, 0);
    // G2: 128 <- 64, fragment-norm(L1); writers: out ch [0,64) from Y1
    k_gemm_h<128, 128, 64, 4, 256, true, 1><<<dim3(GXG + WB, 1), 256, sm2>>>(
        pW2, pY1, pY2, pScH + 0, pShH + 0,
        pSum + 256, pSq + 256, g2, b2, pSc + 256, pSh + 256, pScH + 256, pShH + 256, pCnt + 1,
        out, pY1, pSc + 0, pSh + 0, nullptr, GXG, GXG, 64, 0);
    // G3: 128 <- 128, fragment-norm(L2); writers: out ch [128,256) from Y2
    k_gemm_h<128, 128, 128, 4, 256, true, 1><<<dim3(GXG + WB, 1), 256, sm3>>>(
        pW3, pY2, pY3, pScH + 256, pShH + 256,
        pSum + 512, pSq + 512, g3, b3, pSc + 512, pSh + 512, pScH + 512, pShH + 512, pCnt + 2,
        out, pY2, pSc + 256, pSh + 256, nullptr, GXG, GXG, 128, 128);
    // G4: 256 <- 128, fragment-norm(L3), grid.y = 2, no writers
    k_gemm_h<128, 256, 128, 4, 256, true, 0><<<dim3(GXG, 2), 256, sm3>>>(
        pW4, pY3, pY4, pScH + 512, pShH + 512,
        pSum + 768, pSq + 768, g4, b4, pSc + 768, pSh + 768, pScH + 768, pShH + 768, pCnt + 3,
        out, nullptr, nullptr, nullptr, nullptr, GXG, GXG * 2, 0, 0);
    // out ch [384,640) from Y4
    k_out<<<2048, 256>>>(pY4, 3, 256, 384, out);
}

// round 17
// speedup vs baseline: 1.1647x; 1.1248x over previous
#include <cuda_runtime.h>
#include <cuda_fp16.h>
#include <math.h>

#define B_    16
#define NPTS  2048
#define PCTR  256
#define KNB   32
#define HW    1920
#define INFEA 64
#define MTOT  131072
#define EPSBN 1e-5f
#define DIST_ 0.5f
#define OUTSTRIDE 5242880   // 640*8192

// ---------------- scratch ----------------
__device__ __half g_X0h[96 * MTOT];   // channels 67..95 stay zero
__device__ __half g_Y1h[64 * MTOT];
__device__ __half g_Y2h[128 * MTOT];
__device__ __half g_Y3h[128 * MTOT];
__device__ __half g_Y4h[256 * MTOT];
__device__ float  g_imgT[B_ * HW * 192];    // pixel-major fused img1+img2
__device__ __half g_featT[B_ * NPTS * 64];  // pixel-major feat (half)
__device__ int    g_idx[MTOT];
__device__ int    g_ridx[MTOT];
__device__ float  g_vmask[B_ * PCTR];
__device__ __half g_Wp1h[64 * 96];
__device__ __half g_Wp2h[128 * 64];
__device__ __half g_Wp3h[128 * 128];
__device__ __half g_Wp4h[256 * 128];
__device__ float  g_sum[4][256];
__device__ float  g_sq[4][256];
__device__ float  g_sc[4][256];
__device__ float  g_sh[4][256];
__device__ __half g_scH[4][256];
__device__ __half g_shH[4][256];
__device__ unsigned g_cnt[4];

__device__ __forceinline__ void cp16(void* dst_smem, const void* src) {
    unsigned d = (unsigned)__cvta_generic_to_shared(dst_smem);
    asm volatile("cp.async.cg.shared.global [%0], [%1], 16;" :: "r"(d), "l"(src));
}
__device__ __forceinline__ void ldsm_x4(unsigned* r, unsigned a) {
    asm volatile("ldmatrix.sync.aligned.m8n8.x4.shared.b16 {%0,%1,%2,%3}, [%4];"
        : "=r"(r[0]), "=r"(r[1]), "=r"(r[2]), "=r"(r[3]) : "r"(a));
}
__device__ __forceinline__ void ldsm_x4_t(unsigned* r, unsigned a) {
    asm volatile("ldmatrix.sync.aligned.m8n8.x4.trans.shared.b16 {%0,%1,%2,%3}, [%4];"
        : "=r"(r[0]), "=r"(r[1]), "=r"(r[2]), "=r"(r[3]) : "r"(a));
}
__device__ __forceinline__ unsigned nrm2(unsigned v, unsigned s, unsigned t) {
    __half2 r = __hfma2(*(__half2*)&v, *(__half2*)&s, *(__half2*)&t);
    r = __hmax2(r, __half2(__half(0.f), __half(0.f)));
    return *(unsigned*)&r;
}

// ---------------- weight packing helper ----------------
__device__ __forceinline__ void packW(const float* w, __half* dst,
                                      int M, int CIN, int CINP, int tid, int nthr)
{
    const int tot = M * CINP;
    for (int i = tid; i < tot; i += nthr) {
        const int m = i / CINP, k = i - m * CINP;
        dst[i] = __float2half((k < CIN) ? w[m * CIN + k] : 0.f);
    }
}

// ---------------- fused prologue: ball query + weight pack + transposes ----------------
// blocks [0,16):    depth-ball query (b = blockIdx.x)
// blocks [16,48):   weight packing
// blocks [48,...):  img transpose tiles (16*60*6) then feat tiles (16*64*2)
#define PRE_IDX   16
#define PRE_PREP  32
#define PRE_IMG   (B_ * 60 * 6)
#define PRE_FEAT  (B_ * 64 * 2)
#define PRE_TOTAL (PRE_IDX + PRE_PREP + PRE_IMG + PRE_FEAT)

__global__ void __launch_bounds__(256)
k_pre(const float* __restrict__ pc, const float* __restrict__ npc,
      const int* __restrict__ qv1, const float* __restrict__ feat,
      const float* __restrict__ img1, const float* __restrict__ img2,
      const float* __restrict__ w1, const float* __restrict__ w2,
      const float* __restrict__ w3, const float* __restrict__ w4)
{
    __shared__ float zs[NPTS];          // reused as transpose tile [32][33]
    __shared__ int   stage[8][32];
    const int bid = blockIdx.x;
    const int t   = threadIdx.x;

    if (bid < PRE_IDX) {
        // ---- ball query ----
        const int b = bid;
        if (b == 0) {
            float* ps = &g_sum[0][0];
            float* pq = &g_sq[0][0];
            for (int i = t; i < 4 * 256; i += 256) { ps[i] = 0.f; pq[i] = 0.f; }
            if (t < 4) g_cnt[t] = 0u;
        }
        for (int i = t; i < NPTS; i += 256) zs[i] = pc[(b * 3 + 2) * NPTS + i];
        __syncthreads();

        const int w = t >> 5, lane = t & 31;
        for (int jj = 0; jj < 32; jj++) {
            const int j = w * 32 + jj;
            const float cz = npc[(b * 3 + 2) * PCTR + j];
            int cnt = 0;
            for (int c = 0; c < NPTS / 32; c++) {
                const int n = c * 32 + lane;
                const bool hit = fabsf(zs[n] - cz) < DIST_;
                const unsigned bal = __ballot_sync(0xffffffffu, hit);
                if (hit) {
                    const int pos = cnt + __popc(bal & ((1u << lane) - 1u));
                    if (pos < 32) stage[w][pos] = n;
                }
                cnt += __popc(bal);
                if (cnt >= 32) break;
            }
            __syncwarp();
            const int cc = min(cnt, 32);
            const int first = (cnt > 0) ? stage[w][0] : 0;
            const int v = (lane < cc) ? stage[w][lane] : first;
            const int gbase = (b * PCTR + j) * KNB;
            g_idx[gbase + lane]  = v;
            g_ridx[gbase + lane] = qv1[b * NPTS + v];
            if (lane == 0) g_vmask[b * PCTR + j] = (cnt > 0) ? 1.f : 0.f;
            __syncwarp();
        }
        return;
    }

    if (bid < PRE_IDX + PRE_PREP) {
        // ---- weight packing ----
        const int tid = (bid - PRE_IDX) * 256 + t;
        const int nthr = PRE_PREP * 256;
        packW(w1, g_Wp1h, 64, 67, 96, tid, nthr);
        packW(w2, g_Wp2h, 128, 64, 64, tid, nthr);
        packW(w3, g_Wp3h, 128, 128, 128, tid, nthr);
        packW(w4, g_Wp4h, 256, 128, 128, tid, nthr);
        return;
    }

    // ---- transposes (32x32 tile per block, 256 threads / 4 row-passes) ----
    float (*tile)[33] = (float(*)[33])zs;
    const int tx = t & 31, ty8 = t >> 5;

    int tt = bid - PRE_IDX - PRE_PREP;
    if (tt < PRE_IMG) {
        const int b = tt / 360;
        const int r = tt - b * 360;
        const int pt = r / 6, ct = r - pt * 6;
        const int p0 = pt * 32, c0 = ct * 32;
        for (int yy = ty8; yy < 32; yy += 8) {
            const int c = c0 + yy;
            const float* src = (c < 64) ? &img1[(size_t)(b * 64 + c) * HW]
                                        : &img2[(size_t)(b * 128 + (c - 64)) * HW];
            tile[yy][tx] = src[p0 + tx];
        }
        __syncthreads();
        for (int yy = ty8; yy < 32; yy += 8)
            g_imgT[((size_t)b * HW + p0 + yy) * 192 + c0 + tx] = tile[tx][yy];
    } else {
        tt -= PRE_IMG;
        const int b = tt / 128;
        const int r = tt - b * 128;
        const int pt = r >> 1, ct = r & 1;
        const int p0 = pt * 32, c0 = ct * 32;
        for (int yy = ty8; yy < 32; yy += 8)
            tile[yy][tx] = feat[(size_t)(b * 64 + c0 + yy) * NPTS + p0 + tx];
        __syncthreads();
        for (int yy = ty8; yy < 32; yy += 8)
            g_featT[((size_t)b * NPTS + p0 + yy) * 64 + c0 + tx] =
                __float2half(tile[tx][yy]);
    }
}

// ---------------- gather X0 (half): coalesced rows from featT ----------------
__global__ void k_gather(const float* __restrict__ pc,
                         const float* __restrict__ npc)
{
    __shared__ __align__(16) __half sm[64 * 32];
    __shared__ int    s_idx[32];
    __shared__ float  s_np[3];
    const int g = blockIdx.x;
    const int b = g >> 8;
    const int j = g & 255;
    const int t = threadIdx.x;
    const int mbase = g * KNB;

    if (t < 32) s_idx[t] = g_idx[mbase + t];
    if (t >= 32 && t < 35) s_np[t - 32] = npc[(b * 3 + (t - 32)) * PCTR + j];
    __syncthreads();

    // pc channels (3 x 32)
    if (t < 96) {
        const int c = t >> 5, k = t & 31;
        g_X0h[c * MTOT + mbase + k] =
            __float2half(pc[(b * 3 + c) * NPTS + s_idx[k]] - s_np[c]);
    }

    // feat: k = lane, q = warp -> conflict-light STS
    {
        const int k = t & 31, q = t >> 5;
        const uint4 v = *(const uint4*)&g_featT[((size_t)b * NPTS + s_idx[k]) * 64 + q * 8];
        const __half* hv = (const __half*)&v;
#pragma unroll
        for (int jj = 0; jj < 8; jj++) sm[(q * 8 + jj) * 32 + k] = hv[jj];
    }
    __syncthreads();

    // write X0 channel-major: 64 ch x 4 uint4
    {
        const int c = t >> 2, q = t & 3;
        *(uint4*)&g_X0h[(3 + c) * MTOT + mbase + q * 8] = *(uint4*)&sm[c * 32 + q * 8];
    }
}

// ---------------- multi-tile fp16 TC GEMM + embedded writer blocks ----------------
// WMODE 0: pure GEMM. WMODE 1: writers emit out = relu(wsc*wY+wsh)*vm.
// WMODE 2: writers emit rgb1/rgb2 from pixel-major imgT (coalesced).
template <int BM, int CTOT, int CIN, int TILES, int THREADS, bool NORM_IN, int WMODE>
__global__ void __launch_bounds__(THREADS)
k_gemm_h(const __half* __restrict__ Wp, const __half* __restrict__ X,
         __half* __restrict__ Y,
         const __half* __restrict__ iscH, const __half* __restrict__ ishH,
         float* __restrict__ osum, float* __restrict__ osq,
         const float* __restrict__ gam, const float* __restrict__ bet,
         float* __restrict__ sc, float* __restrict__ sh,
         __half* __restrict__ scH, __half* __restrict__ shH,
         unsigned* __restrict__ cnt,
         float* __restrict__ out,
         const __half* __restrict__ wY,
         const float* __restrict__ wsc, const float* __restrict__ wsh,
         const float* __restrict__ imgT,
         int GXG, int ngemm, int wC, int wcbase)
{
    constexpr int BN = 128, BK = 32, PIPE = 3;
    constexpr int NITER = CIN / BK;
    constexpr int TOT = TILES * NITER;
    constexpr int WROW = CIN + 8;
    constexpr int BROW = BN + 8;
    constexpr int WARPS_M = THREADS / 128;
    constexpr int WTM = BM / WARPS_M;
    constexpr int MI = WTM / 16;
    constexpr int WCH = CIN / 8;

    const int tid = threadIdx.x;
    extern __shared__ __align__(16) __half dsm[];

    // ---------- embedded writer blocks ----------
    if (WMODE != 0 && (int)blockIdx.x >= GXG) {
        const int wb  = blockIdx.x - GXG;
        const int WBn = gridDim.x - GXG;
        if (WMODE == 1) {
            const int T = wC * (MTOT / 8);
            for (int e = wb * THREADS + tid; e < T; e += WBn * THREADS) {
                const int c = e / (MTOT / 8);
                const int m = (e - c * (MTOT / 8)) * 8;
                const uint4 r = *(const uint4*)&wY[(size_t)c * MTOT + m];
                const __half* h = (const __half*)&r;
                const float s = wsc[c], t = wsh[c];
                const float vm = g_vmask[m >> 5];
                const int bb = m >> 13, rem = m & 8191;
                float* op = &out[(long)bb * OUTSTRIDE + (long)(wcbase + c) * 8192 + rem];
                *(float4*)op = make_float4(
                    fmaxf(__half2float(h[0]) * s + t, 0.f) * vm,
                    fmaxf(__half2float(h[1]) * s + t, 0.f) * vm,
                    fmaxf(__half2float(h[2]) * s + t, 0.f) * vm,
                    fmaxf(__half2float(h[3]) * s + t, 0.f) * vm);
                *(float4*)(op + 4) = make_float4(
                    fmaxf(__half2float(h[4]) * s + t, 0.f) * vm,
                    fmaxf(__half2float(h[5]) * s + t, 0.f) * vm,
                    fmaxf(__half2float(h[6]) * s + t, 0.f) * vm,
                    fmaxf(__half2float(h[7]) * s + t, 0.f) * vm);
            }
        } else {
            // rgb writer: coalesced rows from imgT, smem-staged transpose to out
            float* sm = (float*)dsm;                 // [192][33] stage
            int*   rp = (int*)(sm + 192 * 33);       // 32 pixel ids
            float* vmp = sm + 192 * 33 + 32;
            for (int g0 = wb; g0 < B_ * PCTR; g0 += WBn) {
                const int b = g0 >> 8, j = g0 & 255;
                if (tid < 32) rp[tid] = g_ridx[g0 * KNB + tid];
                if (tid == 32) vmp[0] = g_vmask[g0];
                __syncthreads();
                const float vm = vmp[0];
                for (int e = tid; e < 32 * 48; e += THREADS) {
                    const int k = e / 48, c4 = e - k * 48;
                    const float4 v =
                        ((const float4*)&imgT[((size_t)b * HW + rp[k]) * 192])[c4];
                    sm[(c4 * 4 + 0) * 33 + k] = v.x;
                    sm[(c4 * 4 + 1) * 33 + k] = v.y;
                    sm[(c4 * 4 + 2) * 33 + k] = v.z;
                    sm[(c4 * 4 + 3) * 33 + k] = v.w;
                }
                __syncthreads();
                const long ob = (long)b * OUTSTRIDE + (long)j * 32;
                for (int e = tid; e < 192 * 8; e += THREADS) {
                    const int c = e >> 3, q = e & 7;
                    const int oc = (c < 64) ? 64 + c : 192 + c;   // 256+(c-64)
                    const float* sp = &sm[c * 33 + q * 4];
                    float4 o = make_float4(sp[0] * vm, sp[1] * vm, sp[2] * vm, sp[3] * vm);
                    *(float4*)&out[ob + (long)oc * 8192 + q * 4] = o;
                }
                __syncthreads();
            }
        }
        return;
    }

    // ---------- GEMM blocks ----------
    __half* Ws = dsm;                               // BM * WROW
    __half* Bs = Ws + BM * WROW;                    // PIPE * BK * BROW
    __half* sS = Bs + PIPE * BK * BROW;             // CIN
    __half* sT = sS + CIN;                          // CIN
    __shared__ int s_last;

    const int lane = tid & 31;
    const int warp = tid >> 5;
    const int wm0  = (warp >> 2) * WTM;
    const int wn0  = (warp & 3) * 32;
    const int bn0  = blockIdx.x * (BN * TILES);
    const int bm0  = blockIdx.y * BM;
    const int grp  = lane >> 2;
    const int tig  = lane & 3;

    const unsigned ws_u = (unsigned)__cvta_generic_to_shared(Ws);
    const unsigned bs_u = (unsigned)__cvta_generic_to_shared(Bs);

    for (int f = tid; f < BM * WCH; f += THREADS) {
        const int m = f / WCH, ch = f % WCH;
        cp16(&Ws[m * WROW + ch * 8], &Wp[(size_t)(bm0 + m) * CIN + ch * 8]);
    }
    if (NORM_IN) {
        for (int e = tid; e < CIN; e += THREADS) { sS[e] = iscH[e]; sT[e] = ishH[e]; }
    }
    asm volatile("cp.async.commit_group;");

    auto cpB = [&](int g) {
        const int stg = g % PIPE;
        const int tile = g / NITER, it = g - tile * NITER;
        const int nb = bn0 + tile * BN;
        for (int e = tid; e < BK * (BN / 8); e += THREADS) {
            const int kk = e >> 4, ch = e & 15;
            cp16(&Bs[(stg * BK + kk) * BROW + ch * 8],
                 &X[(size_t)(it * BK + kk) * MTOT + nb + ch * 8]);
        }
    };
#pragma unroll
    for (int s = 0; s < PIPE - 1; s++) {
        if (s < TOT) cpB(s);
        asm volatile("cp.async.commit_group;");
    }
    asm volatile("cp.async.wait_group %0;" :: "n"(PIPE - 2));
    __syncthreads();

    float acc[MI][4][4];
#pragma unroll
    for (int mi = 0; mi < MI; mi++)
#pragma unroll
        for (int ni = 0; ni < 4; ni++)
#pragma unroll
            for (int r = 0; r < 4; r++) acc[mi][ni][r] = 0.f;

    float sSr[MI][2], sQr[MI][2];
#pragma unroll
    for (int mi = 0; mi < MI; mi++) {
        sSr[mi][0] = sSr[mi][1] = 0.f;
        sQr[mi][0] = sQr[mi][1] = 0.f;
    }

    const int a_row = (lane & 7) + ((lane >> 3) & 1) * 8;
    const int a_kq  = ((lane >> 4) & 1) * 8;
    const int b_kr  = ((lane >> 3) & 1) * 8 + (lane & 7);
    const int b_nq  = ((lane >> 4) & 1) * 8;

    for (int g = 0; g < TOT; g++) {
        const int stg = g % PIPE;
        const int tile = g / NITER, it = g - tile * NITER;
        if (g + PIPE - 1 < TOT) cpB(g + PIPE - 1);
        asm volatile("cp.async.commit_group;");

#pragma unroll
        for (int kk = 0; kk < 2; kk++) {
            const int kbase = it * BK + kk * 16;
            unsigned a[MI][4], bfr[4][2];
#pragma unroll
            for (int mi = 0; mi < MI; mi++) {
                const unsigned addr = ws_u +
                    (((wm0 + mi * 16 + a_row) * WROW) + kbase + a_kq) * 2;
                ldsm_x4(a[mi], addr);
            }
#pragma unroll
            for (int ni2 = 0; ni2 < 2; ni2++) {
                unsigned t4[4];
                const unsigned addr = bs_u + ((stg * BK + kk * 16 + b_kr) * BROW +
                                              wn0 + ni2 * 16 + b_nq) * 2;
                ldsm_x4_t(t4, addr);
                bfr[ni2 * 2][0] = t4[0]; bfr[ni2 * 2][1] = t4[1];
                bfr[ni2 * 2 + 1][0] = t4[2]; bfr[ni2 * 2 + 1][1] = t4[3];
            }
            if (NORM_IN) {
                const int k0 = kbase + 2 * tig;
                const unsigned s0 = *(const unsigned*)&sS[k0];
                const unsigned t0 = *(const unsigned*)&sT[k0];
                const unsigned s1 = *(const unsigned*)&sS[k0 + 8];
                const unsigned t1 = *(const unsigned*)&sT[k0 + 8];
#pragma unroll
                for (int ni = 0; ni < 4; ni++) {
                    bfr[ni][0] = nrm2(bfr[ni][0], s0, t0);
                    bfr[ni][1] = nrm2(bfr[ni][1], s1, t1);
                }
            }
#pragma unroll
            for (int mi = 0; mi < MI; mi++)
#pragma unroll
                for (int ni = 0; ni < 4; ni++) {
                    asm volatile(
                        "mma.sync.aligned.m16n8k16.row.col.f32.f16.f16.f32 "
                        "{%0,%1,%2,%3}, {%4,%5,%6,%7}, {%8,%9}, {%0,%1,%2,%3};"
                        : "+f"(acc[mi][ni][0]), "+f"(acc[mi][ni][1]),
                          "+f"(acc[mi][ni][2]), "+f"(acc[mi][ni][3])
                        : "r"(a[mi][0]), "r"(a[mi][1]), "r"(a[mi][2]), "r"(a[mi][3]),
                          "r"(bfr[ni][0]), "r"(bfr[ni][1]));
                }
        }

        if (it == NITER - 1) {
            const int nb = bn0 + tile * BN;
#pragma unroll
            for (int mi = 0; mi < MI; mi++) {
                const int r1 = wm0 + mi * 16 + grp;
                const int r2 = r1 + 8;
#pragma unroll
                for (int ni = 0; ni < 4; ni++) {
                    const int col = nb + wn0 + ni * 8 + tig * 2;
                    const float c0 = acc[mi][ni][0], c1 = acc[mi][ni][1];
                    const float c2 = acc[mi][ni][2], c3 = acc[mi][ni][3];
                    *(__half2*)&Y[(size_t)(bm0 + r1) * MTOT + col] = __floats2half2_rn(c0, c1);
                    *(__half2*)&Y[(size_t)(bm0 + r2) * MTOT + col] = __floats2half2_rn(c2, c3);
                    sSr[mi][0] += c0 + c1;  sQr[mi][0] += c0 * c0 + c1 * c1;
                    sSr[mi][1] += c2 + c3;  sQr[mi][1] += c2 * c2 + c3 * c3;
                    acc[mi][ni][0] = 0.f; acc[mi][ni][1] = 0.f;
                    acc[mi][ni][2] = 0.f; acc[mi][ni][3] = 0.f;
                }
            }
        }
        asm volatile("cp.async.wait_group %0;" :: "n"(PIPE - 2));
        __syncthreads();
    }

    // ---- epilogue: block stats reduction (aliases B smem) ----
    float* redS = (float*)Bs;
    float* redQ = redS + BM;
    for (int e = tid; e < BM; e += THREADS) { redS[e] = 0.f; redQ[e] = 0.f; }
    __syncthreads();
#pragma unroll
    for (int mi = 0; mi < MI; mi++) {
        const int r1 = wm0 + mi * 16 + grp;
        atomicAdd(&redS[r1], sSr[mi][0]);
        atomicAdd(&redQ[r1], sQr[mi][0]);
        atomicAdd(&redS[r1 + 8], sSr[mi][1]);
        atomicAdd(&redQ[r1 + 8], sQr[mi][1]);
    }
    __syncthreads();
    for (int e = tid; e < BM; e += THREADS) {
        atomicAdd(&osum[bm0 + e], redS[e]);
        atomicAdd(&osq[bm0 + e], redQ[e]);
    }

    // ---- last GEMM block finalizes BN scale/shift ----
    __threadfence();
    __syncthreads();
    if (tid == 0) {
        const unsigned done = atomicAdd(cnt, 1u);
        s_last = (done == (unsigned)(ngemm - 1)) ? 1 : 0;
    }
    __syncthreads();
    if (s_last) {
        __threadfence();
        for (int c = tid; c < CTOT; c += THREADS) {
            const float m = osum[c] * (1.f / (float)MTOT);
            const float v = osq[c] * (1.f / (float)MTOT) - m * m;
            const float s = gam[c] * rsqrtf(v + EPSBN);
            const float t = bet[c] - m * s;
            sc[c] = s;
            sh[c] = t;
            scH[c] = __float2half(s);
            shH[c] = __float2half(t);
        }
    }
}

// ---------------- out writer: out[cbase..cbase+C) = relu(s*Y+t)*vm (fp32) ----------------
__global__ void k_out(const __half* __restrict__ Y, int layer, int C, int cbase,
                      float* __restrict__ out)
{
    const int T = C * (MTOT / 8);
    for (int e = blockIdx.x * blockDim.x + threadIdx.x; e < T;
         e += gridDim.x * blockDim.x) {
        const int c = e / (MTOT / 8);
        const int m = (e - c * (MTOT / 8)) * 8;
        const uint4 r = *(const uint4*)&Y[(size_t)c * MTOT + m];
        const __half* h = (const __half*)&r;
        const float s = g_sc[layer][c], t = g_sh[layer][c];
        const float vm = g_vmask[m >> 5];
        const int bb = m >> 13, rem = m & 8191;
        float* op = &out[(long)bb * OUTSTRIDE + (long)(cbase + c) * 8192 + rem];
        *(float4*)op = make_float4(
            fmaxf(__half2float(h[0]) * s + t, 0.f) * vm,
            fmaxf(__half2float(h[1]) * s + t, 0.f) * vm,
            fmaxf(__half2float(h[2]) * s + t, 0.f) * vm,
            fmaxf(__half2float(h[3]) * s + t, 0.f) * vm);
        *(float4*)(op + 4) = make_float4(
            fmaxf(__half2float(h[4]) * s + t, 0.f) * vm,
            fmaxf(__half2float(h[5]) * s + t, 0.f) * vm,
            fmaxf(__half2float(h[6]) * s + t, 0.f) * vm,
            fmaxf(__half2float(h[7]) * s + t, 0.f) * vm);
    }
}

// ---------------- launch ----------------
extern "C" void kernel_launch(void* const* d_in, const int* in_sizes, int n_in,
                              void* d_out, int out_size)
{
    const float* pc   = (const float*)d_in[0];
    const float* feat = (const float*)d_in[1];
    const float* img1 = (const float*)d_in[2];
    const float* img2 = (const float*)d_in[3];
    const int*   qv1  = (const int*)d_in[5];
    const float* npc  = (const float*)d_in[6];
    const float* w1 = (const float*)d_in[7];
    const float* g1 = (const float*)d_in[8];
    const float* b1 = (const float*)d_in[9];
    const float* w2 = (const float*)d_in[10];
    const float* g2 = (const float*)d_in[11];
    const float* b2 = (const float*)d_in[12];
    const float* w3 = (const float*)d_in[13];
    const float* g3 = (const float*)d_in[14];
    const float* b3 = (const float*)d_in[15];
    const float* w4 = (const float*)d_in[16];
    const float* g4 = (const float*)d_in[17];
    const float* b4 = (const float*)d_in[18];
    float* out = (float*)d_out;

    __half *pX0, *pY1, *pY2, *pY3, *pY4;
    __half *pW1, *pW2, *pW3, *pW4, *pScH, *pShH;
    float *pSum, *pSq, *pSc, *pSh, *pImgT;
    unsigned *pCnt;
    cudaGetSymbolAddress((void**)&pX0, g_X0h);
    cudaGetSymbolAddress((void**)&pY1, g_Y1h);
    cudaGetSymbolAddress((void**)&pY2, g_Y2h);
    cudaGetSymbolAddress((void**)&pY3, g_Y3h);
    cudaGetSymbolAddress((void**)&pY4, g_Y4h);
    cudaGetSymbolAddress((void**)&pW1, g_Wp1h);
    cudaGetSymbolAddress((void**)&pW2, g_Wp2h);
    cudaGetSymbolAddress((void**)&pW3, g_Wp3h);
    cudaGetSymbolAddress((void**)&pW4, g_Wp4h);
    cudaGetSymbolAddress((void**)&pSum, g_sum);
    cudaGetSymbolAddress((void**)&pSq,  g_sq);
    cudaGetSymbolAddress((void**)&pSc,  g_sc);
    cudaGetSymbolAddress((void**)&pSh,  g_sh);
    cudaGetSymbolAddress((void**)&pScH, g_scH);
    cudaGetSymbolAddress((void**)&pShH, g_shH);
    cudaGetSymbolAddress((void**)&pCnt, g_cnt);
    cudaGetSymbolAddress((void**)&pImgT, g_imgT);

    auto smemSz = [](int BM, int CIN) {
        int gemm = (BM * (CIN + 8) + 3 * 32 * (128 + 8) + 2 * CIN) * 2;
        int wrt  = (192 * 33 + 40) * 4;   // rgb writer stage
        return gemm > wrt ? gemm : wrt;
    };
    const int sm1 = smemSz(64, 96);
    const int sm2 = smemSz(128, 64);
    const int sm3 = smemSz(128, 128);

    static bool attr_done = false;
    if (!attr_done) {
        cudaFuncSetAttribute(k_gemm_h<64, 64, 96, 4, 256, false, 2>,
                             cudaFuncAttributeMaxDynamicSharedMemorySize, sm1);
        cudaFuncSetAttribute(k_gemm_h<128, 128, 64, 4, 256, true, 1>,
                             cudaFuncAttributeMaxDynamicSharedMemorySize, sm2);
        cudaFuncSetAttribute(k_gemm_h<128, 128, 128, 4, 256, true, 1>,
                             cudaFuncAttributeMaxDynamicSharedMemorySize, sm3);
        cudaFuncSetAttribute(k_gemm_h<128, 256, 128, 4, 256, true, 0>,
                             cudaFuncAttributeMaxDynamicSharedMemorySize, sm3);
        attr_done = true;
    }

    // fused prologue: ball query + weight packing + img/feat transposes
    k_pre<<<PRE_TOTAL, 256>>>(pc, npc, qv1, feat, img1, img2, w1, w2, w3, w4);
    k_gather<<<B_ * PCTR, 256>>>(pc, npc);

    const int GXG = MTOT / (128 * 4);    // 256 gemm blocks, 4 tiles each
    const int WB1 = 512;
    const int WB  = 256;

    // G1: 64 <- 96(pad of 67); writers: rgb1/rgb2 -> out ch [64,128) & [256,384)
    k_gemm_h<64, 64, 96, 4, 256, false, 2><<<dim3(GXG + WB1, 1), 256, sm1>>>(
        pW1, pX0, pY1, nullptr, nullptr,
        pSum + 0, pSq + 0, g1, b1, pSc + 0, pSh + 0, pScH + 0, pShH + 0, pCnt + 0,
        out, nullptr, nullptr, nullptr, pImgT, GXG, GXG, 0, 0);
    // G2: 128 <- 64, fragment-norm(L1); writers: out ch [0,64) from Y1
    k_gemm_h<128, 128, 64, 4, 256, true, 1><<<dim3(GXG + WB, 1), 256, sm2>>>(
        pW2, pY1, pY2, pScH + 0, pShH + 0,
        pSum + 256, pSq + 256, g2, b2, pSc + 256, pSh + 256, pScH + 256, pShH + 256, pCnt + 1,
        out, pY1, pSc + 0, pSh + 0, nullptr, GXG, GXG, 64, 0);
    // G3: 128 <- 128, fragment-norm(L2); writers: out ch [128,256) from Y2
    k_gemm_h<128, 128, 128, 4, 256, true, 1><<<dim3(GXG + WB, 1), 256, sm3>>>(
        pW3, pY2, pY3, pScH + 256, pShH + 256,
        pSum + 512, pSq + 512, g3, b3, pSc + 512, pSh + 512, pScH + 512, pShH + 512, pCnt + 2,
        out, pY2, pSc + 256, pSh + 256, nullptr, GXG, GXG, 128, 128);
    // G4: 256 <- 128, fragment-norm(L3), grid.y = 2, no writers
    k_gemm_h<128, 256, 128, 4, 256, true, 0><<<dim3(GXG, 2), 256, sm3>>>(
        pW4, pY3, pY4, pScH + 512, pShH + 512,
        pSum + 768, pSq + 768, g4, b4, pSc + 768, pSh + 768, pScH + 768, pShH + 768, pCnt + 3,
        out, nullptr, nullptr, nullptr, nullptr, GXG, GXG * 2, 0, 0);
    // out ch [384,640) from Y4
    k_out<<<2048, 256>>>(pY4, 3, 256, 384, out);
}